// round 1
// baseline (speedup 1.0000x reference)
#include <cuda_runtime.h>
#include <math.h>

#define BDIM 32
#define TDIM 512
#define SDIM 1024
#define DDIM 1024

// scratch for h_t = input @ W_in^T : [B*T, D] = 64 MB (static device global; no allocs)
__device__ float g_h[(size_t)BDIM * TDIM * DDIM];

// ---------- packed f32x2 helpers (Blackwell-only 2x fp32 path) ----------
__device__ __forceinline__ unsigned long long dup2(float a) {
    unsigned long long r;
    asm("mov.b64 %0, {%1, %1};" : "=l"(r) : "f"(a));
    return r;
}
__device__ __forceinline__ unsigned long long fma2(unsigned long long a,
                                                   unsigned long long b,
                                                   unsigned long long c) {
    unsigned long long d;
    asm("fma.rn.f32x2 %0, %1, %2, %3;" : "=l"(d) : "l"(a), "l"(b), "l"(c));
    return d;
}
__device__ __forceinline__ float2 unpack2(unsigned long long v) {
    float2 f;
    asm("mov.b64 {%0, %1}, %2;" : "=f"(f.x), "=f"(f.y) : "l"(v));
    return f;
}

// ---------------------------------------------------------------------------
// Generic 128x128 tiled GEMM, BK=16, 256 threads, 8x8 per thread, f32x2 core.
// TRANSB=true : C[m,n] = sum_k A[m,k] * B[n,k]   (NT, dot of rows)
// TRANSB=false: C[m,n] = sum_k A[m,k] * B[k,n]   (NN)
// Optional tanh epilogue. blockIdx.z batches with per-operand strides.
// All dims assumed multiples of tile sizes (true for this problem).
// ---------------------------------------------------------------------------
template <bool TRANSB, bool TANH>
__global__ void __launch_bounds__(256) gemm128(
    const float* __restrict__ Ag, int lda, long long strideA,
    const float* __restrict__ Bg, int ldb, long long strideB,
    float* __restrict__ Cg, int ldc, long long strideC,
    int K)
{
    __shared__ float As[2][16][128];
    __shared__ float Bs[2][16][128];

    const int bz = blockIdx.z;
    const float* A  = Ag + (long long)bz * strideA;
    const float* Bp = Bg + (long long)bz * strideB;
    float*       C  = Cg + (long long)bz * strideC;

    const int n0  = blockIdx.x * 128;
    const int m0  = blockIdx.y * 128;
    const int tid = threadIdx.x;
    const int tx4 = (tid & 15) * 4;
    const int ty4 = (tid >> 4) * 4;

    unsigned long long acc[8][4];
#pragma unroll
    for (int i = 0; i < 8; i++)
#pragma unroll
        for (int j = 0; j < 4; j++) acc[i][j] = 0ull;

    float4 ra[2], rb[2];

    auto loadA = [&](int k0) {
#pragma unroll
        for (int i = 0; i < 2; i++) {
            int e = tid + i * 256;
            int r = e >> 2, c = e & 3;
            ra[i] = *reinterpret_cast<const float4*>(&A[(long long)(m0 + r) * lda + k0 + c * 4]);
        }
    };
    auto loadB = [&](int k0) {
#pragma unroll
        for (int i = 0; i < 2; i++) {
            int e = tid + i * 256;
            if (TRANSB) {
                int r = e >> 2, c = e & 3;
                rb[i] = *reinterpret_cast<const float4*>(&Bp[(long long)(n0 + r) * ldb + k0 + c * 4]);
            } else {
                int r = e >> 5, c = e & 31;
                rb[i] = *reinterpret_cast<const float4*>(&Bp[(long long)(k0 + r) * ldb + n0 + c * 4]);
            }
        }
    };
    auto stA = [&](int buf) {
#pragma unroll
        for (int i = 0; i < 2; i++) {
            int e = tid + i * 256;
            int r = e >> 2, c = e & 3;
            As[buf][c * 4 + 0][r] = ra[i].x;
            As[buf][c * 4 + 1][r] = ra[i].y;
            As[buf][c * 4 + 2][r] = ra[i].z;
            As[buf][c * 4 + 3][r] = ra[i].w;
        }
    };
    auto stB = [&](int buf) {
#pragma unroll
        for (int i = 0; i < 2; i++) {
            int e = tid + i * 256;
            if (TRANSB) {
                int r = e >> 2, c = e & 3;
                Bs[buf][c * 4 + 0][r] = rb[i].x;
                Bs[buf][c * 4 + 1][r] = rb[i].y;
                Bs[buf][c * 4 + 2][r] = rb[i].z;
                Bs[buf][c * 4 + 3][r] = rb[i].w;
            } else {
                int r = e >> 5, c = e & 31;
                *reinterpret_cast<float4*>(&Bs[buf][r][c * 4]) = rb[i];
            }
        }
    };

    loadA(0); loadB(0); stA(0); stB(0);
    __syncthreads();

    const int kT = K >> 4;
    for (int kt = 0; kt < kT; kt++) {
        int cur = kt & 1;
        if (kt + 1 < kT) { loadA((kt + 1) << 4); loadB((kt + 1) << 4); }
#pragma unroll
        for (int kk = 0; kk < 16; kk++) {
            float4 a0 = *reinterpret_cast<const float4*>(&As[cur][kk][ty4]);
            float4 a1 = *reinterpret_cast<const float4*>(&As[cur][kk][ty4 + 64]);
            const unsigned long long* bp0 =
                reinterpret_cast<const unsigned long long*>(&Bs[cur][kk][tx4]);
            const unsigned long long* bp1 =
                reinterpret_cast<const unsigned long long*>(&Bs[cur][kk][tx4 + 64]);
            unsigned long long b0 = bp0[0], b1 = bp0[1], b2 = bp1[0], b3 = bp1[1];
            unsigned long long ad[8] = { dup2(a0.x), dup2(a0.y), dup2(a0.z), dup2(a0.w),
                                         dup2(a1.x), dup2(a1.y), dup2(a1.z), dup2(a1.w) };
#pragma unroll
            for (int i = 0; i < 8; i++) {
                acc[i][0] = fma2(ad[i], b0, acc[i][0]);
                acc[i][1] = fma2(ad[i], b1, acc[i][1]);
                acc[i][2] = fma2(ad[i], b2, acc[i][2]);
                acc[i][3] = fma2(ad[i], b3, acc[i][3]);
            }
        }
        if (kt + 1 < kT) {
            __syncthreads();
            stA(cur ^ 1); stB(cur ^ 1);
            __syncthreads();
        }
    }

#pragma unroll
    for (int i = 0; i < 8; i++) {
        int row = m0 + ((i < 4) ? (ty4 + i) : (ty4 + 64 + i - 4));
#pragma unroll
        for (int g = 0; g < 2; g++) {
            float2 p0 = unpack2(acc[i][g * 2 + 0]);
            float2 p1 = unpack2(acc[i][g * 2 + 1]);
            float4 v = make_float4(p0.x, p0.y, p1.x, p1.y);
            if (TANH) {
                v.x = tanhf(v.x); v.y = tanhf(v.y);
                v.z = tanhf(v.z); v.w = tanhf(v.w);
            }
            *reinterpret_cast<float4*>(&C[(long long)row * ldc + n0 + tx4 + g * 64]) = v;
        }
    }
}

// ---------------- softmax over contiguous rows of length 1024 ----------------
__global__ void __launch_bounds__(256) softmax1024(float* __restrict__ p)
{
    __shared__ float red[8];
    long long row = blockIdx.x;
    float* r = p + row * 1024;
    int tid = threadIdx.x;
    float4 v = reinterpret_cast<float4*>(r)[tid];

    float m = fmaxf(fmaxf(v.x, v.y), fmaxf(v.z, v.w));
#pragma unroll
    for (int o = 16; o > 0; o >>= 1) m = fmaxf(m, __shfl_xor_sync(0xffffffffu, m, o));
    if ((tid & 31) == 0) red[tid >> 5] = m;
    __syncthreads();
    float bm = red[0];
#pragma unroll
    for (int i = 1; i < 8; i++) bm = fmaxf(bm, red[i]);
    __syncthreads();

    v.x = __expf(v.x - bm); v.y = __expf(v.y - bm);
    v.z = __expf(v.z - bm); v.w = __expf(v.w - bm);
    float s = v.x + v.y + v.z + v.w;
#pragma unroll
    for (int o = 16; o > 0; o >>= 1) s += __shfl_xor_sync(0xffffffffu, s, o);
    if ((tid & 31) == 0) red[tid >> 5] = s;
    __syncthreads();
    float bs = 0.f;
#pragma unroll
    for (int i = 0; i < 8; i++) bs += red[i];
    float inv = 1.0f / bs;
    v.x *= inv; v.y *= inv; v.z *= inv; v.w *= inv;
    reinterpret_cast<float4*>(r)[tid] = v;
}

// ------ copy input[b,t,d] into concat_c[t,b,D+d] (second half of concat) ------
__global__ void __launch_bounds__(256) copy_input_to_concat(
    const float* __restrict__ in, float* __restrict__ concat)
{
    const long long DQ = DDIM / 4;
    long long g = (long long)blockIdx.x * blockDim.x + threadIdx.x; // float4 idx over B*T*D/4
    long long b   = g / (TDIM * DQ);
    long long rem = g - b * (TDIM * DQ);
    long long t   = rem / DQ;
    long long dq  = rem - t * DQ;
    float4 v = reinterpret_cast<const float4*>(in)[g];
    long long dst = ((t * BDIM + b) * (2 * DDIM) + DDIM) / 4 + dq;
    reinterpret_cast<float4*>(concat)[dst] = v;
}

extern "C" void kernel_launch(void* const* d_in, const int* in_sizes, int n_in,
                              void* d_out, int out_size)
{
    (void)in_sizes; (void)n_in; (void)out_size;
    const float* input   = (const float*)d_in[0];   // [B,T,D]
    const float* context = (const float*)d_in[1];   // [B,S,D]
    const float* W_in    = (const float*)d_in[2];   // [D,D]
    const float* W_out   = (const float*)d_in[3];   // [D,2D]

    float* out    = (float*)d_out;
    float* attn   = out;                                        // [T,B,D]
    float* alignv = out + (long long)TDIM * BDIM * DDIM;        // [T,B,S]
    float* concat = alignv + (long long)TDIM * BDIM * SDIM;     // [T,B,2D]

    float* hbuf;
    cudaGetSymbolAddress((void**)&hbuf, g_h);

    dim3 blk(256);

    // 1) h = input @ W_in^T : [B*T, D] x [D, D]  (NT)
    gemm128<true, false><<<dim3(8, 128, 1), blk>>>(
        input, DDIM, 0LL, W_in, DDIM, 0LL, hbuf, DDIM, 0LL, DDIM);

    // 2) align[b] = h[b] @ context[b]^T : [T, S], K=D  (NT, batched)
    //    written straight into [T,B,S] layout: C base = alignv + b*S, ldc = B*S
    gemm128<true, false><<<dim3(8, 4, 32), blk>>>(
        hbuf, DDIM, (long long)TDIM * DDIM,
        context, DDIM, (long long)SDIM * DDIM,
        alignv, BDIM * SDIM, (long long)SDIM, DDIM);

    // 3) softmax over S (rows are contiguous in [T,B,S])
    softmax1024<<<TDIM * BDIM, 256>>>(alignv);

    // 4) input -> concat_c second half
    copy_input_to_concat<<<(BDIM * TDIM * DDIM / 4) / 256, 256>>>(input, concat);

    // 5) c[b] = align_v[b] @ context[b] : [T, D], K=S  (NN, batched)
    //    written into concat_c first half: C base = concat + b*2D, ldc = B*2D
    gemm128<false, false><<<dim3(8, 4, 32), blk>>>(
        alignv, BDIM * SDIM, (long long)SDIM,
        context, DDIM, (long long)SDIM * DDIM,
        concat, BDIM * 2 * DDIM, (long long)(2 * DDIM), SDIM);

    // 6) attn = tanh(concat @ W_out^T) : [T*B, D], K=2D  (NT + tanh)
    gemm128<true, true><<<dim3(8, 128, 1), blk>>>(
        concat, 2 * DDIM, 0LL, W_out, 2 * DDIM, 0LL, attn, DDIM, 0LL, 2 * DDIM);
}

// round 3
// speedup vs baseline: 2.5908x; 2.5908x over previous
#include <cuda_runtime.h>
#include <cuda_fp16.h>
#include <cstdint>
#include <math.h>

#define BD 32
#define TD 512
#define SD 1024
#define DD 1024

typedef __half h16;

// ---------------- scratch (device globals; no runtime allocation) ----------------
__device__ h16 g_in_hi [(size_t)BD*TD*DD],   g_in_lo [(size_t)BD*TD*DD];
__device__ h16 g_ctx_hi[(size_t)BD*SD*DD],   g_ctx_lo[(size_t)BD*SD*DD];
__device__ h16 g_ctxT_hi[(size_t)BD*DD*SD],  g_ctxT_lo[(size_t)BD*DD*SD];
__device__ h16 g_win_hi[(size_t)DD*DD],      g_win_lo[(size_t)DD*DD];
__device__ h16 g_wout_hi[(size_t)DD*2*DD],   g_wout_lo[(size_t)DD*2*DD];
__device__ h16 g_h_hi  [(size_t)BD*TD*DD],   g_h_lo  [(size_t)BD*TD*DD];
__device__ h16 g_av_hi [(size_t)TD*BD*SD],   g_av_lo [(size_t)TD*BD*SD];
__device__ h16 g_cc_hi [(size_t)TD*BD*2*DD], g_cc_lo [(size_t)TD*BD*2*DD];

// ---------------- PTX helpers ----------------
__device__ __forceinline__ uint32_t smem_u32(const void* p) {
    uint32_t a;
    asm("{ .reg .u64 t; cvta.to.shared.u64 t, %1; cvt.u32.u64 %0, t; }" : "=r"(a) : "l"(p));
    return a;
}
__device__ __forceinline__ void cp16(uint32_t dst, const void* src) {
    asm volatile("cp.async.cg.shared.global [%0], [%1], 16;\n" :: "r"(dst), "l"(src) : "memory");
}
#define CP_COMMIT() asm volatile("cp.async.commit_group;\n" ::: "memory")
#define CP_WAIT(n)  asm volatile("cp.async.wait_group %0;\n" :: "n"(n) : "memory")
#define SW128(o)    ((o) ^ (((o) >> 3) & 0x70))

__device__ __forceinline__ void ldsm4(uint32_t* r, uint32_t addr) {
    asm volatile("ldmatrix.sync.aligned.m8n8.x4.shared.b16 {%0,%1,%2,%3}, [%4];"
                 : "=r"(r[0]), "=r"(r[1]), "=r"(r[2]), "=r"(r[3]) : "r"(addr));
}
__device__ __forceinline__ void mma16816(float* c, const uint32_t* a, const uint32_t* b) {
    asm volatile(
        "mma.sync.aligned.m16n8k16.row.col.f32.f16.f16.f32 "
        "{%0,%1,%2,%3}, {%4,%5,%6,%7}, {%8,%9}, {%0,%1,%2,%3};"
        : "+f"(c[0]), "+f"(c[1]), "+f"(c[2]), "+f"(c[3])
        : "r"(a[0]), "r"(a[1]), "r"(a[2]), "r"(a[3]), "r"(b[0]), "r"(b[1]));
}
__device__ __forceinline__ void split2(float a, float b, __half2& H, __half2& L) {
    __half ha = __float2half_rn(a), hb = __float2half_rn(b);
    H = __halves2half2(ha, hb);
    L = __halves2half2(__float2half_rn(a - __half2float(ha)),
                       __float2half_rn(b - __half2float(hb)));
}

// ---------------- fp16-split HMMA GEMM ----------------
// C[m,n] = sum_k A[m,k]*B[n,k] (NT). A,B given as fp16 (hi,lo) pairs of fp32.
// CTA tile 128x128, K-chunk 64 (128B rows, SW128), 2-stage cp.async, 8 warps @64x32.
static constexpr int ST_BYTES = 65536;           // Ahi16K Alo16K Bhi16K Blo16K
static constexpr int SMEM_TOT = 2 * ST_BYTES;    // 128 KB

template <bool WF32, bool WTANH, bool WPAIR>
__global__ void __launch_bounds__(256) gemm_hmma(
    const h16* __restrict__ Ahi_, const h16* __restrict__ Alo_,
    long long lda, long long sA,
    const h16* __restrict__ Bhi_, const h16* __restrict__ Blo_,
    long long ldb, long long sB,
    float* __restrict__ C_, long long ldc, long long sC,
    h16* __restrict__ Phi_, h16* __restrict__ Plo_,
    long long ldp, long long sP,
    int K)
{
    extern __shared__ char smem[];
    const uint32_t sb = smem_u32(smem);
    const int tid = threadIdx.x, wid = tid >> 5, l = tid & 31;
    const long long bz = blockIdx.z;
    const h16* Ahi = Ahi_ + bz * sA;
    const h16* Alo = Alo_ + bz * sA;
    const h16* Bhi = Bhi_ + bz * sB;
    const h16* Blo = Blo_ + bz * sB;
    const long long m0 = (long long)blockIdx.y * 128;
    const long long n0 = (long long)blockIdx.x * 128;

    const int wm = wid & 1;        // 2 M groups of 64
    const int wn = wid >> 1;       // 4 N groups of 32

    // per-lane ldmatrix offsets (bytes within a 128x128B tile)
    const int laneA = ((l & 7) + ((l >> 3) & 1) * 8) * 128 + ((l >> 4) & 1) * 16;
    const int laneB = ((l & 7) + ((l >> 4) & 1) * 8) * 128 + ((l >> 3) & 1) * 16;

    float acc[4][4][4];
#pragma unroll
    for (int i = 0; i < 4; i++)
#pragma unroll
        for (int j = 0; j < 4; j++)
#pragma unroll
            for (int v = 0; v < 4; v++) acc[i][j][v] = 0.f;

    auto load_chunk = [&](int stage, int kt) {
        const long long k0 = (long long)kt << 6;
        const uint32_t st = sb + stage * ST_BYTES;
#pragma unroll
        for (int i = 0; i < 4; i++) {            // 1024 16B chunks per matrix
            int ch = tid + (i << 8);
            int r = ch >> 3, c = ch & 7;
            uint32_t sw = SW128(r * 128 + c * 16);
            long long ga = (m0 + r) * lda + k0 + c * 8;
            long long gb = (n0 + r) * ldb + k0 + c * 8;
            cp16(st + sw,          Ahi + ga);
            cp16(st + 16384 + sw,  Alo + ga);
            cp16(st + 32768 + sw,  Bhi + gb);
            cp16(st + 49152 + sw,  Blo + gb);
        }
        CP_COMMIT();
    };

    const int KT = K >> 6;
    load_chunk(0, 0);
    for (int kt = 0; kt < KT; kt++) {
        const int s = kt & 1;
        if (kt + 1 < KT) { load_chunk(s ^ 1, kt + 1); CP_WAIT(1); }
        else             { CP_WAIT(0); }
        __syncthreads();

        const uint32_t aH = sb + s * ST_BYTES;
        const uint32_t aL = aH + 16384;
        const uint32_t bH = aH + 32768;
        const uint32_t bL = aH + 49152;
#pragma unroll
        for (int kk = 0; kk < 4; kk++) {
            uint32_t Ah[4][4], Al[4][4], Bh[2][4], Bl[2][4];
#pragma unroll
            for (int mt = 0; mt < 4; mt++) {
                int off = (wm * 64 + mt * 16) * 128 + kk * 32 + laneA;
                ldsm4(Ah[mt], aH + SW128(off));
                ldsm4(Al[mt], aL + SW128(off));
            }
#pragma unroll
            for (int pt = 0; pt < 2; pt++) {
                int off = (wn * 32 + pt * 16) * 128 + kk * 32 + laneB;
                ldsm4(Bh[pt], bH + SW128(off));
                ldsm4(Bl[pt], bL + SW128(off));
            }
#pragma unroll
            for (int mt = 0; mt < 4; mt++)
#pragma unroll
                for (int nt = 0; nt < 4; nt++) {
                    const uint32_t* bh = &Bh[nt >> 1][(nt & 1) * 2];
                    const uint32_t* bl = &Bl[nt >> 1][(nt & 1) * 2];
                    mma16816(acc[mt][nt], Ah[mt], bh);
                    mma16816(acc[mt][nt], Ah[mt], bl);
                    mma16816(acc[mt][nt], Al[mt], bh);
                }
        }
        __syncthreads();
    }

    // ---------------- epilogue ----------------
    float* C = C_ + bz * sC;
    h16* Ph = Phi_ + bz * sP;
    h16* Pl = Plo_ + bz * sP;
    const int q = l >> 2, tl = l & 3;
#pragma unroll
    for (int mt = 0; mt < 4; mt++) {
#pragma unroll
        for (int nt = 0; nt < 4; nt++) {
            long long r0 = m0 + wm * 64 + mt * 16 + q;
            long long col = n0 + wn * 32 + nt * 8 + tl * 2;
            float d0 = acc[mt][nt][0], d1 = acc[mt][nt][1];
            float d2 = acc[mt][nt][2], d3 = acc[mt][nt][3];
            if (WTANH) { d0 = tanhf(d0); d1 = tanhf(d1); d2 = tanhf(d2); d3 = tanhf(d3); }
            if (WF32) {
                *reinterpret_cast<float2*>(C + r0 * ldc + col)       = make_float2(d0, d1);
                *reinterpret_cast<float2*>(C + (r0 + 8) * ldc + col) = make_float2(d2, d3);
            }
            if (WPAIR) {
                __half2 H, L;
                split2(d0, d1, H, L);
                *reinterpret_cast<__half2*>(Ph + r0 * ldp + col) = H;
                *reinterpret_cast<__half2*>(Pl + r0 * ldp + col) = L;
                split2(d2, d3, H, L);
                *reinterpret_cast<__half2*>(Ph + (r0 + 8) * ldp + col) = H;
                *reinterpret_cast<__half2*>(Pl + (r0 + 8) * ldp + col) = L;
            }
        }
    }
}

// ---------------- fp32 -> (hi,lo) fp16 split ----------------
__global__ void __launch_bounds__(256) split_kernel(const float* __restrict__ src,
                                                    h16* __restrict__ hi,
                                                    h16* __restrict__ lo, long long n)
{
    long long i4 = ((long long)blockIdx.x * 256 + threadIdx.x) * 4;
    if (i4 >= n) return;
    float4 v = *reinterpret_cast<const float4*>(src + i4);
    __half2 H0, L0, H1, L1;
    split2(v.x, v.y, H0, L0);
    split2(v.z, v.w, H1, L1);
    *reinterpret_cast<__half2*>(hi + i4)     = H0;
    *reinterpret_cast<__half2*>(hi + i4 + 2) = H1;
    *reinterpret_cast<__half2*>(lo + i4)     = L0;
    *reinterpret_cast<__half2*>(lo + i4 + 2) = L1;
}

// -------- context transpose + split: ctxT[b,d,s] = ctx[b,s,d] --------
__global__ void __launch_bounds__(256) transpose_split_kernel(const float* __restrict__ ctx,
                                                              h16* __restrict__ tHi,
                                                              h16* __restrict__ tLo)
{
    __shared__ float tile[32][33];
    const int b = blockIdx.z;
    const int d0 = blockIdx.x * 32, s0 = blockIdx.y * 32;
    const int tx = threadIdx.x & 31, ty = threadIdx.x >> 5;
    const float* src = ctx + (size_t)b * SD * DD;
#pragma unroll
    for (int j = 0; j < 4; j++)
        tile[ty + j * 8][tx] = src[(size_t)(s0 + ty + j * 8) * DD + d0 + tx];
    __syncthreads();
    h16* dh = tHi + (size_t)b * DD * SD;
    h16* dl = tLo + (size_t)b * DD * SD;
#pragma unroll
    for (int j = 0; j < 4; j++) {
        float v = tile[tx][ty + j * 8];
        __half h = __float2half_rn(v);
        dh[(size_t)(d0 + ty + j * 8) * SD + s0 + tx] = h;
        dl[(size_t)(d0 + ty + j * 8) * SD + s0 + tx] =
            __float2half_rn(v - __half2float(h));
    }
}

// ---------------- softmax (rows of 1024) + fp16-pair emit ----------------
__global__ void __launch_bounds__(256) softmax1024(float* __restrict__ p,
                                                   h16* __restrict__ hi,
                                                   h16* __restrict__ lo)
{
    __shared__ float red[8];
    const long long row = blockIdx.x;
    float* r = p + row * 1024;
    const int tid = threadIdx.x;
    float4 v = reinterpret_cast<float4*>(r)[tid];

    float m = fmaxf(fmaxf(v.x, v.y), fmaxf(v.z, v.w));
#pragma unroll
    for (int o = 16; o > 0; o >>= 1) m = fmaxf(m, __shfl_xor_sync(0xffffffffu, m, o));
    if ((tid & 31) == 0) red[tid >> 5] = m;
    __syncthreads();
    float bm = red[0];
#pragma unroll
    for (int i = 1; i < 8; i++) bm = fmaxf(bm, red[i]);
    __syncthreads();

    v.x = __expf(v.x - bm); v.y = __expf(v.y - bm);
    v.z = __expf(v.z - bm); v.w = __expf(v.w - bm);
    float s = v.x + v.y + v.z + v.w;
#pragma unroll
    for (int o = 16; o > 0; o >>= 1) s += __shfl_xor_sync(0xffffffffu, s, o);
    if ((tid & 31) == 0) red[tid >> 5] = s;
    __syncthreads();
    float bs = 0.f;
#pragma unroll
    for (int i = 0; i < 8; i++) bs += red[i];
    const float inv = 1.0f / bs;
    v.x *= inv; v.y *= inv; v.z *= inv; v.w *= inv;
    reinterpret_cast<float4*>(r)[tid] = v;

    const size_t off = (size_t)row * 1024 + tid * 4;
    __half2 H0, L0, H1, L1;
    split2(v.x, v.y, H0, L0);
    split2(v.z, v.w, H1, L1);
    *reinterpret_cast<__half2*>(hi + off)     = H0;
    *reinterpret_cast<__half2*>(hi + off + 2) = H1;
    *reinterpret_cast<__half2*>(lo + off)     = L0;
    *reinterpret_cast<__half2*>(lo + off + 2) = L1;
}

// ------ input[b,t,d] -> concat_c[t,b,D+d] (fp32 + fp16 pair) ------
__global__ void __launch_bounds__(256) copy_input_to_concat(const float* __restrict__ in,
                                                            float* __restrict__ concat,
                                                            h16* __restrict__ chi,
                                                            h16* __restrict__ clo)
{
    const long long DQ = DD / 4;
    long long g = (long long)blockIdx.x * blockDim.x + threadIdx.x;
    long long b   = g / (TD * DQ);
    long long rem = g - b * (TD * DQ);
    long long t   = rem / DQ;
    long long dq  = rem - t * DQ;
    float4 v = reinterpret_cast<const float4*>(in)[g];
    long long dstq = ((t * BD + b) * (2 * DD) + DD) / 4 + dq;
    reinterpret_cast<float4*>(concat)[dstq] = v;
    const size_t e = (size_t)dstq * 4;
    __half2 H0, L0, H1, L1;
    split2(v.x, v.y, H0, L0);
    split2(v.z, v.w, H1, L1);
    *reinterpret_cast<__half2*>(chi + e)     = H0;
    *reinterpret_cast<__half2*>(chi + e + 2) = H1;
    *reinterpret_cast<__half2*>(clo + e)     = L0;
    *reinterpret_cast<__half2*>(clo + e + 2) = L1;
}

extern "C" void kernel_launch(void* const* d_in, const int* in_sizes, int n_in,
                              void* d_out, int out_size)
{
    (void)in_sizes; (void)n_in; (void)out_size;
    const float* input   = (const float*)d_in[0];   // [B,T,D]
    const float* context = (const float*)d_in[1];   // [B,S,D]
    const float* W_in    = (const float*)d_in[2];   // [D,D]
    const float* W_out   = (const float*)d_in[3];   // [D,2D]

    float* out    = (float*)d_out;
    float* attn   = out;                                   // [T,B,D]
    float* alignv = out + (long long)TD * BD * DD;         // [T,B,S]
    float* concat = alignv + (long long)TD * BD * SD;      // [T,B,2D]

    h16 *in_hi, *in_lo, *ctx_hi, *ctx_lo, *ctxT_hi, *ctxT_lo;
    h16 *win_hi, *win_lo, *wout_hi, *wout_lo;
    h16 *h_hi, *h_lo, *av_hi, *av_lo, *cc_hi, *cc_lo;
    cudaGetSymbolAddress((void**)&in_hi,  g_in_hi);   cudaGetSymbolAddress((void**)&in_lo,  g_in_lo);
    cudaGetSymbolAddress((void**)&ctx_hi, g_ctx_hi);  cudaGetSymbolAddress((void**)&ctx_lo, g_ctx_lo);
    cudaGetSymbolAddress((void**)&ctxT_hi,g_ctxT_hi); cudaGetSymbolAddress((void**)&ctxT_lo,g_ctxT_lo);
    cudaGetSymbolAddress((void**)&win_hi, g_win_hi);  cudaGetSymbolAddress((void**)&win_lo, g_win_lo);
    cudaGetSymbolAddress((void**)&wout_hi,g_wout_hi); cudaGetSymbolAddress((void**)&wout_lo,g_wout_lo);
    cudaGetSymbolAddress((void**)&h_hi,   g_h_hi);    cudaGetSymbolAddress((void**)&h_lo,   g_h_lo);
    cudaGetSymbolAddress((void**)&av_hi,  g_av_hi);   cudaGetSymbolAddress((void**)&av_lo,  g_av_lo);
    cudaGetSymbolAddress((void**)&cc_hi,  g_cc_hi);   cudaGetSymbolAddress((void**)&cc_lo,  g_cc_lo);

    cudaFuncSetAttribute(gemm_hmma<false, false, true>,
                         cudaFuncAttributeMaxDynamicSharedMemorySize, SMEM_TOT);
    cudaFuncSetAttribute(gemm_hmma<true, false, false>,
                         cudaFuncAttributeMaxDynamicSharedMemorySize, SMEM_TOT);
    cudaFuncSetAttribute(gemm_hmma<true, false, true>,
                         cudaFuncAttributeMaxDynamicSharedMemorySize, SMEM_TOT);
    cudaFuncSetAttribute(gemm_hmma<true, true, false>,
                         cudaFuncAttributeMaxDynamicSharedMemorySize, SMEM_TOT);

    // operand conversions
    split_kernel<<<(BD * TD * DD) / 1024, 256>>>(input,   in_hi,  in_lo,  (long long)BD * TD * DD);
    split_kernel<<<(BD * SD * DD) / 1024, 256>>>(context, ctx_hi, ctx_lo, (long long)BD * SD * DD);
    split_kernel<<<(DD * DD) / 1024, 256>>>(W_in,  win_hi,  win_lo,  (long long)DD * DD);
    split_kernel<<<(DD * 2 * DD) / 1024, 256>>>(W_out, wout_hi, wout_lo, (long long)DD * 2 * DD);
    transpose_split_kernel<<<dim3(DD / 32, SD / 32, BD), 256>>>(context, ctxT_hi, ctxT_lo);

    // 1) h = input @ W_in^T : [16384,1024], K=1024 -> fp16 pair out
    gemm_hmma<false, false, true><<<dim3(DD / 128, (BD * TD) / 128, 1), 256, SMEM_TOT>>>(
        in_hi, in_lo, DD, 0LL, win_hi, win_lo, DD, 0LL,
        nullptr, 0LL, 0LL, h_hi, h_lo, DD, 0LL, DD);

    // 2) align[b] = h[b] @ ctx[b]^T : [512,1024] per batch, K=1024 -> fp32 into [T,B,S]
    gemm_hmma<true, false, false><<<dim3(SD / 128, TD / 128, BD), 256, SMEM_TOT>>>(
        h_hi, h_lo, DD, (long long)TD * DD, ctx_hi, ctx_lo, DD, (long long)SD * DD,
        alignv, (long long)BD * SD, (long long)SD, nullptr, nullptr, 0LL, 0LL, DD);

    // 3) softmax over S + fp16 pair
    softmax1024<<<TD * BD, 256>>>(alignv, av_hi, av_lo);

    // 4) input -> concat second half (fp32 + pair)
    copy_input_to_concat<<<(BD * TD * DD / 4) / 256, 256>>>(input, concat, cc_hi, cc_lo);

    // 5) c[b] = av[b] @ ctxT[b]^T : [512,1024] per batch, K=1024(S) -> fp32 + pair into concat halves
    gemm_hmma<true, false, true><<<dim3(DD / 128, TD / 128, BD), 256, SMEM_TOT>>>(
        av_hi, av_lo, (long long)BD * SD, (long long)SD,
        ctxT_hi, ctxT_lo, SD, (long long)DD * SD,
        concat, (long long)BD * 2 * DD, (long long)(2 * DD),
        cc_hi, cc_lo, (long long)BD * 2 * DD, (long long)(2 * DD), SD);

    // 6) attn = tanh(concat @ W_out^T) : [16384,1024], K=2048 -> fp32
    gemm_hmma<true, true, false><<<dim3(DD / 128, (TD * BD) / 128, 1), 256, SMEM_TOT>>>(
        cc_hi, cc_lo, 2 * DD, 0LL, wout_hi, wout_lo, 2 * DD, 0LL,
        attn, DD, 0LL, nullptr, nullptr, 0LL, 0LL, 2 * DD);
}

// round 5
// speedup vs baseline: 2.7846x; 1.0748x over previous
#include <cuda_runtime.h>
#include <cuda_fp16.h>
#include <cstdint>
#include <math.h>

#define BD 32
#define TD 512
#define SD 1024
#define DD 1024

typedef __half h16;

// ---------------- scratch (device globals; no runtime allocation) ----------------
__device__ h16 g_in_hi [(size_t)BD*TD*DD],   g_in_lo [(size_t)BD*TD*DD];
__device__ h16 g_ctx_hi[(size_t)BD*SD*DD],   g_ctx_lo[(size_t)BD*SD*DD];
__device__ h16 g_ctxT_hi[(size_t)BD*DD*SD],  g_ctxT_lo[(size_t)BD*DD*SD];
__device__ h16 g_win_hi[(size_t)DD*DD],      g_win_lo[(size_t)DD*DD];
__device__ h16 g_wout_hi[(size_t)DD*2*DD],   g_wout_lo[(size_t)DD*2*DD];
__device__ h16 g_h_hi  [(size_t)BD*TD*DD],   g_h_lo  [(size_t)BD*TD*DD];
__device__ h16 g_av_hi [(size_t)TD*BD*SD],   g_av_lo [(size_t)TD*BD*SD];
__device__ h16 g_cc_hi [(size_t)TD*BD*2*DD], g_cc_lo [(size_t)TD*BD*2*DD];

// ---------------- PTX helpers ----------------
__device__ __forceinline__ uint32_t smem_u32(const void* p) {
    uint32_t a;
    asm("{ .reg .u64 t; cvta.to.shared.u64 t, %1; cvt.u32.u64 %0, t; }" : "=r"(a) : "l"(p));
    return a;
}
__device__ __forceinline__ void cp16(uint32_t dst, const void* src) {
    asm volatile("cp.async.cg.shared.global [%0], [%1], 16;\n" :: "r"(dst), "l"(src) : "memory");
}
#define CP_COMMIT() asm volatile("cp.async.commit_group;\n" ::: "memory")
#define CP_WAIT(n)  asm volatile("cp.async.wait_group %0;\n" :: "n"(n) : "memory")
#define SW128(o)    ((o) ^ (((o) >> 3) & 0x70))

__device__ __forceinline__ void ldsm4(uint32_t* r, uint32_t addr) {
    asm volatile("ldmatrix.sync.aligned.m8n8.x4.shared.b16 {%0,%1,%2,%3}, [%4];"
                 : "=r"(r[0]), "=r"(r[1]), "=r"(r[2]), "=r"(r[3]) : "r"(addr));
}
__device__ __forceinline__ void mma16816(float* c, const uint32_t* a, const uint32_t* b) {
    asm volatile(
        "mma.sync.aligned.m16n8k16.row.col.f32.f16.f16.f32 "
        "{%0,%1,%2,%3}, {%4,%5,%6,%7}, {%8,%9}, {%0,%1,%2,%3};"
        : "+f"(c[0]), "+f"(c[1]), "+f"(c[2]), "+f"(c[3])
        : "r"(a[0]), "r"(a[1]), "r"(a[2]), "r"(a[3]), "r"(b[0]), "r"(b[1]));
}
__device__ __forceinline__ void split2(float a, float b, __half2& H, __half2& L) {
    __half ha = __float2half_rn(a), hb = __float2half_rn(b);
    H = __halves2half2(ha, hb);
    L = __halves2half2(__float2half_rn(a - __half2float(ha)),
                       __float2half_rn(b - __half2float(hb)));
}

// ---------------- fp16-split HMMA GEMM ----------------
// C[m,n] = sum_k A[m,k]*B[n,k] (NT). A,B fp16 (hi,lo) pairs of fp32.
// CTA tile 128x256, K-chunk 64 (128B SW128 rows), 2-stage cp.async.
// 8 warps as 2(M)x4(N), each warp 64x64. TERMS=3: AhBh+AhBl+AlBh; TERMS=2 drops AlBh.
static constexpr int ST_BYTES = 98304;           // Ahi16K Alo16K Bhi32K Blo32K
static constexpr int SMEM_TOT = 2 * ST_BYTES;    // 192 KB

template <int TERMS, bool WF32, bool WTANH, bool WPAIR>
__global__ void __launch_bounds__(256, 1) gemm_hmma(
    const h16* __restrict__ Ahi_, const h16* __restrict__ Alo_,
    long long lda, long long sA,
    const h16* __restrict__ Bhi_, const h16* __restrict__ Blo_,
    long long ldb, long long sB,
    float* __restrict__ C_, long long ldc, long long sC,
    h16* __restrict__ Phi_, h16* __restrict__ Plo_,
    long long ldp, long long sP,
    int K)
{
    extern __shared__ char smem[];
    const uint32_t sb = smem_u32(smem);
    const int tid = threadIdx.x, wid = tid >> 5, l = tid & 31;
    const long long bz = blockIdx.z;
    const h16* Ahi = Ahi_ + bz * sA;
    const h16* Alo = Alo_ + bz * sA;
    const h16* Bhi = Bhi_ + bz * sB;
    const h16* Blo = Blo_ + bz * sB;
    const long long m0 = (long long)blockIdx.y * 128;
    const long long n0 = (long long)blockIdx.x * 256;

    const int wm = wid & 1;        // 2 M groups of 64
    const int wn = wid >> 1;       // 4 N groups of 64

    // per-lane ldmatrix byte offsets (within a 128B-row tile)
    // A (m16k16): bit3 -> +8 rows, bit4 -> +16B k-chunk
    const int laneA = ((l & 7) + ((l >> 3) & 1) * 8) * 128 + ((l >> 4) & 1) * 16;
    // B (n16k16): bit4 -> +8 rows, bit3 -> +16B k-chunk  (R3-verified mapping)
    const int laneB = ((l & 7) + ((l >> 4) & 1) * 8) * 128 + ((l >> 3) & 1) * 16;

    float acc[4][8][4];
#pragma unroll
    for (int i = 0; i < 4; i++)
#pragma unroll
        for (int j = 0; j < 8; j++)
#pragma unroll
            for (int v = 0; v < 4; v++) acc[i][j][v] = 0.f;

    auto load_chunk = [&](int stage, int kt) {
        const long long k0 = (long long)kt << 6;
        const uint32_t st = sb + stage * ST_BYTES;
#pragma unroll
        for (int i = 0; i < 4; i++) {            // A: 1024 16B chunks per matrix
            int ch = tid + (i << 8);
            int r = ch >> 3, c = ch & 7;
            uint32_t sw = SW128(r * 128 + c * 16);
            long long ga = (m0 + r) * lda + k0 + c * 8;
            cp16(st + sw,         Ahi + ga);
            cp16(st + 16384 + sw, Alo + ga);
        }
#pragma unroll
        for (int i = 0; i < 8; i++) {            // B: 2048 16B chunks per matrix
            int ch = tid + (i << 8);
            int r = ch >> 3, c = ch & 7;
            uint32_t sw = SW128(r * 128 + c * 16);
            long long gb = (n0 + r) * ldb + k0 + c * 8;
            cp16(st + 32768 + sw, Bhi + gb);
            cp16(st + 65536 + sw, Blo + gb);
        }
        CP_COMMIT();
    };

    const int KT = K >> 6;
    load_chunk(0, 0);
    for (int kt = 0; kt < KT; kt++) {
        const int s = kt & 1;
        if (kt + 1 < KT) { load_chunk(s ^ 1, kt + 1); CP_WAIT(1); }
        else             { CP_WAIT(0); }
        __syncthreads();

        const uint32_t aH = sb + s * ST_BYTES;
        const uint32_t aL = aH + 16384;
        const uint32_t bH = aH + 32768;
        const uint32_t bL = aH + 65536;
#pragma unroll
        for (int kk = 0; kk < 4; kk++) {
            uint32_t Ah[4][4], Al[4][4];
#pragma unroll
            for (int mt = 0; mt < 4; mt++) {
                int off = (wm * 64 + mt * 16) * 128 + kk * 32 + laneA;
                ldsm4(Ah[mt], aH + SW128(off));
                if (TERMS == 3) ldsm4(Al[mt], aL + SW128(off));
            }
#pragma unroll
            for (int bh2 = 0; bh2 < 2; bh2++) {   // two 32-col halves of the 64-col warp tile
                uint32_t Bh[2][4], Bl[2][4];
#pragma unroll
                for (int pt = 0; pt < 2; pt++) {
                    int off = (wn * 64 + bh2 * 32 + pt * 16) * 128 + kk * 32 + laneB;
                    ldsm4(Bh[pt], bH + SW128(off));
                    ldsm4(Bl[pt], bL + SW128(off));
                }
#pragma unroll
                for (int mt = 0; mt < 4; mt++)
#pragma unroll
                    for (int j = 0; j < 4; j++) {
                        float* c = acc[mt][bh2 * 4 + j];
                        const uint32_t* bh = &Bh[j >> 1][(j & 1) * 2];
                        const uint32_t* bl = &Bl[j >> 1][(j & 1) * 2];
                        mma16816(c, Ah[mt], bh);
                        mma16816(c, Ah[mt], bl);
                        if (TERMS == 3) mma16816(c, Al[mt], bh);
                    }
            }
        }
        __syncthreads();
    }

    // ---------------- epilogue ----------------
    float* C = C_ + bz * sC;
    h16* Ph = Phi_ + bz * sP;
    h16* Pl = Plo_ + bz * sP;
    const int q = l >> 2, tl = l & 3;
#pragma unroll
    for (int mt = 0; mt < 4; mt++) {
#pragma unroll
        for (int nt = 0; nt < 8; nt++) {
            long long r0 = m0 + wm * 64 + mt * 16 + q;
            long long col = n0 + wn * 64 + nt * 8 + tl * 2;
            float d0 = acc[mt][nt][0], d1 = acc[mt][nt][1];
            float d2 = acc[mt][nt][2], d3 = acc[mt][nt][3];
            if (WTANH) { d0 = tanhf(d0); d1 = tanhf(d1); d2 = tanhf(d2); d3 = tanhf(d3); }
            if (WF32) {
                *reinterpret_cast<float2*>(C + r0 * ldc + col)       = make_float2(d0, d1);
                *reinterpret_cast<float2*>(C + (r0 + 8) * ldc + col) = make_float2(d2, d3);
            }
            if (WPAIR) {
                __half2 H, L;
                split2(d0, d1, H, L);
                *reinterpret_cast<__half2*>(Ph + r0 * ldp + col) = H;
                *reinterpret_cast<__half2*>(Pl + r0 * ldp + col) = L;
                split2(d2, d3, H, L);
                *reinterpret_cast<__half2*>(Ph + (r0 + 8) * ldp + col) = H;
                *reinterpret_cast<__half2*>(Pl + (r0 + 8) * ldp + col) = L;
            }
        }
    }
}

// ---------------- fp32 -> (hi,lo) fp16 split ----------------
__global__ void __launch_bounds__(256) split_kernel(const float* __restrict__ src,
                                                    h16* __restrict__ hi,
                                                    h16* __restrict__ lo, long long n)
{
    long long i4 = ((long long)blockIdx.x * 256 + threadIdx.x) * 4;
    if (i4 >= n) return;
    float4 v = *reinterpret_cast<const float4*>(src + i4);
    __half2 H0, L0, H1, L1;
    split2(v.x, v.y, H0, L0);
    split2(v.z, v.w, H1, L1);
    *reinterpret_cast<__half2*>(hi + i4)     = H0;
    *reinterpret_cast<__half2*>(hi + i4 + 2) = H1;
    *reinterpret_cast<__half2*>(lo + i4)     = L0;
    *reinterpret_cast<__half2*>(lo + i4 + 2) = L1;
}

// -------- context transpose + split: ctxT[b,d,s] = ctx[b,s,d] --------
__global__ void __launch_bounds__(256) transpose_split_kernel(const float* __restrict__ ctx,
                                                              h16* __restrict__ tHi,
                                                              h16* __restrict__ tLo)
{
    __shared__ float tile[32][33];
    const int b = blockIdx.z;
    const int d0 = blockIdx.x * 32, s0 = blockIdx.y * 32;
    const int tx = threadIdx.x & 31, ty = threadIdx.x >> 5;
    const float* src = ctx + (size_t)b * SD * DD;
#pragma unroll
    for (int j = 0; j < 4; j++)
        tile[ty + j * 8][tx] = src[(size_t)(s0 + ty + j * 8) * DD + d0 + tx];
    __syncthreads();
    h16* dh = tHi + (size_t)b * DD * SD;
    h16* dl = tLo + (size_t)b * DD * SD;
#pragma unroll
    for (int j = 0; j < 4; j++) {
        float v = tile[tx][ty + j * 8];
        __half h = __float2half_rn(v);
        dh[(size_t)(d0 + ty + j * 8) * SD + s0 + tx] = h;
        dl[(size_t)(d0 + ty + j * 8) * SD + s0 + tx] =
            __float2half_rn(v - __half2float(h));
    }
}

// ---------------- softmax (rows of 1024) + fp16-pair emit ----------------
__global__ void __launch_bounds__(256) softmax1024(float* __restrict__ p,
                                                   h16* __restrict__ hi,
                                                   h16* __restrict__ lo)
{
    __shared__ float red[8];
    const long long row = blockIdx.x;
    float* r = p + row * 1024;
    const int tid = threadIdx.x;
    float4 v = reinterpret_cast<float4*>(r)[tid];

    float m = fmaxf(fmaxf(v.x, v.y), fmaxf(v.z, v.w));
#pragma unroll
    for (int o = 16; o > 0; o >>= 1) m = fmaxf(m, __shfl_xor_sync(0xffffffffu, m, o));
    if ((tid & 31) == 0) red[tid >> 5] = m;
    __syncthreads();
    float bm = red[0];
#pragma unroll
    for (int i = 1; i < 8; i++) bm = fmaxf(bm, red[i]);
    __syncthreads();

    v.x = __expf(v.x - bm); v.y = __expf(v.y - bm);
    v.z = __expf(v.z - bm); v.w = __expf(v.w - bm);
    float s = v.x + v.y + v.z + v.w;
#pragma unroll
    for (int o = 16; o > 0; o >>= 1) s += __shfl_xor_sync(0xffffffffu, s, o);
    if ((tid & 31) == 0) red[tid >> 5] = s;
    __syncthreads();
    float bs = 0.f;
#pragma unroll
    for (int i = 0; i < 8; i++) bs += red[i];
    const float inv = 1.0f / bs;
    v.x *= inv; v.y *= inv; v.z *= inv; v.w *= inv;
    reinterpret_cast<float4*>(r)[tid] = v;

    const size_t off = (size_t)row * 1024 + tid * 4;
    __half2 H0, L0, H1, L1;
    split2(v.x, v.y, H0, L0);
    split2(v.z, v.w, H1, L1);
    *reinterpret_cast<__half2*>(hi + off)     = H0;
    *reinterpret_cast<__half2*>(hi + off + 2) = H1;
    *reinterpret_cast<__half2*>(lo + off)     = L0;
    *reinterpret_cast<__half2*>(lo + off + 2) = L1;
}

// ------ input[b,t,d] -> concat_c[t,b,D+d] (fp32 + fp16 pair) ------
__global__ void __launch_bounds__(256) copy_input_to_concat(const float* __restrict__ in,
                                                            float* __restrict__ concat,
                                                            h16* __restrict__ chi,
                                                            h16* __restrict__ clo)
{
    const long long DQ = DD / 4;
    long long g = (long long)blockIdx.x * blockDim.x + threadIdx.x;
    long long b   = g / (TD * DQ);
    long long rem = g - b * (TD * DQ);
    long long t   = rem / DQ;
    long long dq  = rem - t * DQ;
    float4 v = reinterpret_cast<const float4*>(in)[g];
    long long dstq = ((t * BD + b) * (2 * DD) + DD) / 4 + dq;
    reinterpret_cast<float4*>(concat)[dstq] = v;
    const size_t e = (size_t)dstq * 4;
    __half2 H0, L0, H1, L1;
    split2(v.x, v.y, H0, L0);
    split2(v.z, v.w, H1, L1);
    *reinterpret_cast<__half2*>(chi + e)     = H0;
    *reinterpret_cast<__half2*>(chi + e + 2) = H1;
    *reinterpret_cast<__half2*>(clo + e)     = L0;
    *reinterpret_cast<__half2*>(clo + e + 2) = L1;
}

extern "C" void kernel_launch(void* const* d_in, const int* in_sizes, int n_in,
                              void* d_out, int out_size)
{
    (void)in_sizes; (void)n_in; (void)out_size;
    const float* input   = (const float*)d_in[0];   // [B,T,D]
    const float* context = (const float*)d_in[1];   // [B,S,D]
    const float* W_in    = (const float*)d_in[2];   // [D,D]
    const float* W_out   = (const float*)d_in[3];   // [D,2D]

    float* out    = (float*)d_out;
    float* attn   = out;                                   // [T,B,D]
    float* alignv = out + (long long)TD * BD * DD;         // [T,B,S]
    float* concat = alignv + (long long)TD * BD * SD;      // [T,B,2D]

    h16 *in_hi, *in_lo, *ctx_hi, *ctx_lo, *ctxT_hi, *ctxT_lo;
    h16 *win_hi, *win_lo, *wout_hi, *wout_lo;
    h16 *h_hi, *h_lo, *av_hi, *av_lo, *cc_hi, *cc_lo;
    cudaGetSymbolAddress((void**)&in_hi,  g_in_hi);   cudaGetSymbolAddress((void**)&in_lo,  g_in_lo);
    cudaGetSymbolAddress((void**)&ctx_hi, g_ctx_hi);  cudaGetSymbolAddress((void**)&ctx_lo, g_ctx_lo);
    cudaGetSymbolAddress((void**)&ctxT_hi,g_ctxT_hi); cudaGetSymbolAddress((void**)&ctxT_lo,g_ctxT_lo);
    cudaGetSymbolAddress((void**)&win_hi, g_win_hi);  cudaGetSymbolAddress((void**)&win_lo, g_win_lo);
    cudaGetSymbolAddress((void**)&wout_hi,g_wout_hi); cudaGetSymbolAddress((void**)&wout_lo,g_wout_lo);
    cudaGetSymbolAddress((void**)&h_hi,   g_h_hi);    cudaGetSymbolAddress((void**)&h_lo,   g_h_lo);
    cudaGetSymbolAddress((void**)&av_hi,  g_av_hi);   cudaGetSymbolAddress((void**)&av_lo,  g_av_lo);
    cudaGetSymbolAddress((void**)&cc_hi,  g_cc_hi);   cudaGetSymbolAddress((void**)&cc_lo,  g_cc_lo);

    cudaFuncSetAttribute(gemm_hmma<3, false, false, true>,
                         cudaFuncAttributeMaxDynamicSharedMemorySize, SMEM_TOT);
    cudaFuncSetAttribute(gemm_hmma<3, true, false, false>,
                         cudaFuncAttributeMaxDynamicSharedMemorySize, SMEM_TOT);
    cudaFuncSetAttribute(gemm_hmma<2, true, false, true>,
                         cudaFuncAttributeMaxDynamicSharedMemorySize, SMEM_TOT);
    cudaFuncSetAttribute(gemm_hmma<2, true, true, false>,
                         cudaFuncAttributeMaxDynamicSharedMemorySize, SMEM_TOT);

    // operand conversions
    split_kernel<<<(BD * TD * DD) / 1024, 256>>>(input,   in_hi,  in_lo,  (long long)BD * TD * DD);
    split_kernel<<<(BD * SD * DD) / 1024, 256>>>(context, ctx_hi, ctx_lo, (long long)BD * SD * DD);
    split_kernel<<<(DD * DD) / 1024, 256>>>(W_in,  win_hi,  win_lo,  (long long)DD * DD);
    split_kernel<<<(DD * 2 * DD) / 1024, 256>>>(W_out, wout_hi, wout_lo, (long long)DD * 2 * DD);
    transpose_split_kernel<<<dim3(DD / 32, SD / 32, BD), 256>>>(context, ctxT_hi, ctxT_lo);

    // 1) h = input @ W_in^T : [16384,1024], K=1024 -> fp16 pair out  (3-term: feeds logits)
    gemm_hmma<3, false, false, true><<<dim3(DD / 256, (BD * TD) / 128, 1), 256, SMEM_TOT>>>(
        in_hi, in_lo, DD, 0LL, win_hi, win_lo, DD, 0LL,
        nullptr, 0LL, 0LL, h_hi, h_lo, DD, 0LL, DD);

    // 2) align[b] = h[b] @ ctx[b]^T : K=1024 -> fp32 into [T,B,S]  (3-term: logits)
    gemm_hmma<3, true, false, false><<<dim3(SD / 256, TD / 128, BD), 256, SMEM_TOT>>>(
        h_hi, h_lo, DD, (long long)TD * DD, ctx_hi, ctx_lo, DD, (long long)SD * DD,
        alignv, (long long)BD * SD, (long long)SD, nullptr, nullptr, 0LL, 0LL, DD);

    // 3) softmax over S + fp16 pair
    softmax1024<<<TD * BD, 256>>>(alignv, av_hi, av_lo);

    // 4) input -> concat second half (fp32 + pair)
    copy_input_to_concat<<<(BD * TD * DD / 4) / 256, 256>>>(input, concat, cc_hi, cc_lo);

    // 5) c[b] = av[b] @ ctxT[b]^T : K=1024(S) -> fp32 + pair  (2-term: ~1e-4 rel)
    gemm_hmma<2, true, false, true><<<dim3(DD / 256, TD / 128, BD), 256, SMEM_TOT>>>(
        av_hi, av_lo, (long long)BD * SD, (long long)SD,
        ctxT_hi, ctxT_lo, SD, (long long)DD * SD,
        concat, (long long)BD * 2 * DD, (long long)(2 * DD),
        cc_hi, cc_lo, (long long)BD * 2 * DD, (long long)(2 * DD), SD);

    // 6) attn = tanh(concat @ W_out^T) : K=2048 -> fp32  (2-term: ~1e-4 pre-tanh)
    gemm_hmma<2, true, true, false><<<dim3(DD / 256, (TD * BD) / 128, 1), 256, SMEM_TOT>>>(
        cc_hi, cc_lo, 2 * DD, 0LL, wout_hi, wout_lo, 2 * DD, 0LL,
        attn, DD, 0LL, nullptr, nullptr, 0LL, 0LL, 2 * DD);
}

// round 7
// speedup vs baseline: 2.8884x; 1.0373x over previous
#include <cuda_runtime.h>
#include <cuda_fp16.h>
#include <cstdint>
#include <math.h>

#define BD 32
#define TD 512
#define SD 1024
#define DD 1024

typedef __half h16;

// ---------------- scratch (device globals; no runtime allocation) ----------------
__device__ h16 g_in_hi [(size_t)BD*TD*DD],   g_in_lo [(size_t)BD*TD*DD];
__device__ h16 g_ctx_hi[(size_t)BD*SD*DD],   g_ctx_lo[(size_t)BD*SD*DD];
__device__ h16 g_ctxT_hi[(size_t)BD*DD*SD],  g_ctxT_lo[(size_t)BD*DD*SD];
__device__ h16 g_win_hi[(size_t)DD*DD],      g_win_lo[(size_t)DD*DD];
__device__ h16 g_wout_hi[(size_t)DD*2*DD],   g_wout_lo[(size_t)DD*2*DD];
__device__ h16 g_h_hi  [(size_t)BD*TD*DD],   g_h_lo  [(size_t)BD*TD*DD];
__device__ h16 g_av_hi [(size_t)TD*BD*SD],   g_av_lo [(size_t)TD*BD*SD];
__device__ h16 g_cc_hi [(size_t)TD*BD*2*DD], g_cc_lo [(size_t)TD*BD*2*DD];

// ---------------- PTX helpers ----------------
__device__ __forceinline__ uint32_t smem_u32(const void* p) {
    uint32_t a;
    asm("{ .reg .u64 t; cvta.to.shared.u64 t, %1; cvt.u32.u64 %0, t; }" : "=r"(a) : "l"(p));
    return a;
}
__device__ __forceinline__ void cp16(uint32_t dst, const void* src) {
    asm volatile("cp.async.cg.shared.global [%0], [%1], 16;\n" :: "r"(dst), "l"(src) : "memory");
}
#define CP_COMMIT() asm volatile("cp.async.commit_group;\n" ::: "memory")
#define CP_WAIT(n)  asm volatile("cp.async.wait_group %0;\n" :: "n"(n) : "memory")
#define SW128(o)    ((o) ^ (((o) >> 3) & 0x70))

__device__ __forceinline__ void ldsm4(uint32_t* r, uint32_t addr) {
    asm volatile("ldmatrix.sync.aligned.m8n8.x4.shared.b16 {%0,%1,%2,%3}, [%4];"
                 : "=r"(r[0]), "=r"(r[1]), "=r"(r[2]), "=r"(r[3]) : "r"(addr));
}
__device__ __forceinline__ void mma16816(float* c, const uint32_t* a, const uint32_t* b) {
    asm volatile(
        "mma.sync.aligned.m16n8k16.row.col.f32.f16.f16.f32 "
        "{%0,%1,%2,%3}, {%4,%5,%6,%7}, {%8,%9}, {%0,%1,%2,%3};"
        : "+f"(c[0]), "+f"(c[1]), "+f"(c[2]), "+f"(c[3])
        : "r"(a[0]), "r"(a[1]), "r"(a[2]), "r"(a[3]), "r"(b[0]), "r"(b[1]));
}
__device__ __forceinline__ void split2(float a, float b, __half2& H, __half2& L) {
    __half ha = __float2half_rn(a), hb = __float2half_rn(b);
    H = __halves2half2(ha, hb);
    L = __halves2half2(__float2half_rn(a - __half2float(ha)),
                       __float2half_rn(b - __half2float(hb)));
}

// ---------------- fp16-split HMMA GEMM, occupancy-2 variant ----------------
// C[m,n] = sum_k A[m,k]*B[n,k] (NT). A,B fp16 (hi,lo) pairs of fp32.
// CTA 128x128, warp tile 64x32 (8 warps as 2Mx4N). K-chunk 32 with hi|lo packed
// per 128B row -> stage 32KB; 3-stage cp.async pipeline; 2 CTAs/SM.
static constexpr int ST_BYTES = 32768;           // A 16K (hi|lo packed) + B 16K
static constexpr int SMEM_TOT = 3 * ST_BYTES;    // 96 KB -> 2 CTAs/SM

template <int TERMS, bool WF32, bool WTANH, bool WPAIR>
__global__ void __launch_bounds__(256, 2) gemm_hmma(
    const h16* __restrict__ Ahi_, const h16* __restrict__ Alo_,
    long long lda, long long sA,
    const h16* __restrict__ Bhi_, const h16* __restrict__ Blo_,
    long long ldb, long long sB,
    float* __restrict__ C_, long long ldc, long long sC,
    h16* __restrict__ Phi_, h16* __restrict__ Plo_,
    long long ldp, long long sP,
    int K)
{
    extern __shared__ char smem[];
    const uint32_t sb = smem_u32(smem);
    const int tid = threadIdx.x, wid = tid >> 5, l = tid & 31;
    const long long bz = blockIdx.z;
    const h16* Ahi = Ahi_ + bz * sA;
    const h16* Alo = Alo_ + bz * sA;
    const h16* Bhi = Bhi_ + bz * sB;
    const h16* Blo = Blo_ + bz * sB;
    const long long m0 = (long long)blockIdx.y * 128;
    const long long n0 = (long long)blockIdx.x * 128;

    const int wm = wid & 1;        // 2 M groups of 64
    const int wn = wid >> 1;       // 4 N groups of 32

    // ldmatrix lane byte offsets within a 128B-row tile
    // A (m16k16): bit3 -> +8 rows, bit4 -> +16B k-chunk
    const int laneA = ((l & 7) + ((l >> 3) & 1) * 8) * 128 + ((l >> 4) & 1) * 16;
    // B (n16k16): bit4 -> +8 rows, bit3 -> +16B k-chunk
    const int laneB = ((l & 7) + ((l >> 4) & 1) * 8) * 128 + ((l >> 3) & 1) * 16;

    float acc[4][4][4];
#pragma unroll
    for (int i = 0; i < 4; i++)
#pragma unroll
        for (int j = 0; j < 4; j++)
#pragma unroll
            for (int v = 0; v < 4; v++) acc[i][j][v] = 0.f;

    // row layout: [32 hi fp16 | 32 lo fp16] = 128B, SW128 swizzled
    auto load_chunk = [&](int stage, int kt) {
        const long long k0 = (long long)kt << 5;
        const uint32_t st = sb + stage * ST_BYTES;
#pragma unroll
        for (int i = 0; i < 4; i++) {            // A: 1024 16B chunks
            int ch = tid + (i << 8);
            int r = ch >> 3, c = ch & 7;
            const h16* base = (c < 4) ? Ahi : Alo;
            cp16(st + SW128(r * 128 + c * 16),
                 base + (m0 + r) * lda + k0 + (c & 3) * 8);
        }
#pragma unroll
        for (int i = 0; i < 4; i++) {            // B: 1024 16B chunks
            int ch = tid + (i << 8);
            int r = ch >> 3, c = ch & 7;
            const h16* base = (c < 4) ? Bhi : Blo;
            cp16(st + 16384 + SW128(r * 128 + c * 16),
                 base + (n0 + r) * ldb + k0 + (c & 3) * 8);
        }
        CP_COMMIT();
    };

    const int KT = K >> 5;
    load_chunk(0, 0);
    load_chunk(1, 1);
    int s = 0, ls = 2;
    for (int kt = 0; kt < KT; kt++) {
        if (kt + 2 < KT) {
            load_chunk(ls, kt + 2);
            ls = (ls == 2) ? 0 : ls + 1;
            CP_WAIT(2);
        } else if (kt + 1 < KT) {
            CP_WAIT(1);
        } else {
            CP_WAIT(0);
        }
        __syncthreads();

        const uint32_t aB = sb + s * ST_BYTES;
        const uint32_t bB = aB + 16384;
#pragma unroll
        for (int kk = 0; kk < 2; kk++) {
            uint32_t Bh[2][4], Bl[2][4];
#pragma unroll
            for (int pt = 0; pt < 2; pt++) {
                int off = (wn * 32 + pt * 16) * 128 + kk * 32 + laneB;
                ldsm4(Bh[pt], bB + SW128(off));        // hi half of row
                ldsm4(Bl[pt], bB + SW128(off + 64));   // lo half of row
            }
#pragma unroll
            for (int mt = 0; mt < 4; mt++) {
                int offA = (wm * 64 + mt * 16) * 128 + kk * 32 + laneA;
                uint32_t Ah[4];
                ldsm4(Ah, aB + SW128(offA));
#pragma unroll
                for (int j = 0; j < 4; j++) {
                    float* c = acc[mt][j];
                    mma16816(c, Ah, &Bh[j >> 1][(j & 1) * 2]);
                    mma16816(c, Ah, &Bl[j >> 1][(j & 1) * 2]);
                }
                if (TERMS == 3) {
                    uint32_t Al[4];
                    ldsm4(Al, aB + SW128(offA + 64));
#pragma unroll
                    for (int j = 0; j < 4; j++)
                        mma16816(acc[mt][j], Al, &Bh[j >> 1][(j & 1) * 2]);
                }
            }
        }
        __syncthreads();
        s = (s == 2) ? 0 : s + 1;
    }

    // ---------------- epilogue ----------------
    float* C = C_ + bz * sC;
    h16* Ph = Phi_ + bz * sP;
    h16* Pl = Plo_ + bz * sP;
    const int q = l >> 2, tl = l & 3;
#pragma unroll
    for (int mt = 0; mt < 4; mt++) {
#pragma unroll
        for (int nt = 0; nt < 4; nt++) {
            long long r0 = m0 + wm * 64 + mt * 16 + q;
            long long col = n0 + wn * 32 + nt * 8 + tl * 2;
            float d0 = acc[mt][nt][0], d1 = acc[mt][nt][1];
            float d2 = acc[mt][nt][2], d3 = acc[mt][nt][3];
            if (WTANH) { d0 = tanhf(d0); d1 = tanhf(d1); d2 = tanhf(d2); d3 = tanhf(d3); }
            if (WF32) {
                *reinterpret_cast<float2*>(C + r0 * ldc + col)       = make_float2(d0, d1);
                *reinterpret_cast<float2*>(C + (r0 + 8) * ldc + col) = make_float2(d2, d3);
            }
            if (WPAIR) {
                __half2 H, L;
                split2(d0, d1, H, L);
                *reinterpret_cast<__half2*>(Ph + r0 * ldp + col) = H;
                *reinterpret_cast<__half2*>(Pl + r0 * ldp + col) = L;
                split2(d2, d3, H, L);
                *reinterpret_cast<__half2*>(Ph + (r0 + 8) * ldp + col) = H;
                *reinterpret_cast<__half2*>(Pl + (r0 + 8) * ldp + col) = L;
            }
        }
    }
}

// ---------------- fp32 -> (hi,lo) fp16 split ----------------
__global__ void __launch_bounds__(256) split_kernel(const float* __restrict__ src,
                                                    h16* __restrict__ hi,
                                                    h16* __restrict__ lo, long long n)
{
    long long i4 = ((long long)blockIdx.x * 256 + threadIdx.x) * 4;
    if (i4 >= n) return;
    float4 v = *reinterpret_cast<const float4*>(src + i4);
    __half2 H0, L0, H1, L1;
    split2(v.x, v.y, H0, L0);
    split2(v.z, v.w, H1, L1);
    *reinterpret_cast<__half2*>(hi + i4)     = H0;
    *reinterpret_cast<__half2*>(hi + i4 + 2) = H1;
    *reinterpret_cast<__half2*>(lo + i4)     = L0;
    *reinterpret_cast<__half2*>(lo + i4 + 2) = L1;
}

// -------- context transpose + split: ctxT[b,d,s] = ctx[b,s,d] --------
__global__ void __launch_bounds__(256) transpose_split_kernel(const float* __restrict__ ctx,
                                                              h16* __restrict__ tHi,
                                                              h16* __restrict__ tLo)
{
    __shared__ float tile[32][33];
    const int b = blockIdx.z;
    const int d0 = blockIdx.x * 32, s0 = blockIdx.y * 32;
    const int tx = threadIdx.x & 31, ty = threadIdx.x >> 5;
    const float* src = ctx + (size_t)b * SD * DD;
#pragma unroll
    for (int j = 0; j < 4; j++)
        tile[ty + j * 8][tx] = src[(size_t)(s0 + ty + j * 8) * DD + d0 + tx];
    __syncthreads();
    h16* dh = tHi + (size_t)b * DD * SD;
    h16* dl = tLo + (size_t)b * DD * SD;
#pragma unroll
    for (int j = 0; j < 4; j++) {
        float v = tile[tx][ty + j * 8];
        __half h = __float2half_rn(v);
        dh[(size_t)(d0 + ty + j * 8) * SD + s0 + tx] = h;
        dl[(size_t)(d0 + ty + j * 8) * SD + s0 + tx] =
            __float2half_rn(v - __half2float(h));
    }
}

// ---------------- softmax (rows of 1024) + fp16-pair emit ----------------
__global__ void __launch_bounds__(256) softmax1024(float* __restrict__ p,
                                                   h16* __restrict__ hi,
                                                   h16* __restrict__ lo)
{
    __shared__ float red[8];
    const long long row = blockIdx.x;
    float* r = p + row * 1024;
    const int tid = threadIdx.x;
    float4 v = reinterpret_cast<float4*>(r)[tid];

    float m = fmaxf(fmaxf(v.x, v.y), fmaxf(v.z, v.w));
#pragma unroll
    for (int o = 16; o > 0; o >>= 1) m = fmaxf(m, __shfl_xor_sync(0xffffffffu, m, o));
    if ((tid & 31) == 0) red[tid >> 5] = m;
    __syncthreads();
    float bm = red[0];
#pragma unroll
    for (int i = 1; i < 8; i++) bm = fmaxf(bm, red[i]);
    __syncthreads();

    v.x = __expf(v.x - bm); v.y = __expf(v.y - bm);
    v.z = __expf(v.z - bm); v.w = __expf(v.w - bm);
    float s = v.x + v.y + v.z + v.w;
#pragma unroll
    for (int o = 16; o > 0; o >>= 1) s += __shfl_xor_sync(0xffffffffu, s, o);
    if ((tid & 31) == 0) red[tid >> 5] = s;
    __syncthreads();
    float bs = 0.f;
#pragma unroll
    for (int i = 0; i < 8; i++) bs += red[i];
    const float inv = 1.0f / bs;
    v.x *= inv; v.y *= inv; v.z *= inv; v.w *= inv;
    reinterpret_cast<float4*>(r)[tid] = v;

    const size_t off = (size_t)row * 1024 + tid * 4;
    __half2 H0, L0, H1, L1;
    split2(v.x, v.y, H0, L0);
    split2(v.z, v.w, H1, L1);
    *reinterpret_cast<__half2*>(hi + off)     = H0;
    *reinterpret_cast<__half2*>(hi + off + 2) = H1;
    *reinterpret_cast<__half2*>(lo + off)     = L0;
    *reinterpret_cast<__half2*>(lo + off + 2) = L1;
}

// ------ input[b,t,d] -> concat_c[t,b,D+d] (fp32 + fp16 pair) ------
__global__ void __launch_bounds__(256) copy_input_to_concat(const float* __restrict__ in,
                                                            float* __restrict__ concat,
                                                            h16* __restrict__ chi,
                                                            h16* __restrict__ clo)
{
    const long long DQ = DD / 4;
    long long g = (long long)blockIdx.x * blockDim.x + threadIdx.x;
    long long b   = g / (TD * DQ);
    long long rem = g - b * (TD * DQ);
    long long t   = rem / DQ;
    long long dq  = rem - t * DQ;
    float4 v = reinterpret_cast<const float4*>(in)[g];
    long long dstq = ((t * BD + b) * (2 * DD) + DD) / 4 + dq;
    reinterpret_cast<float4*>(concat)[dstq] = v;
    const size_t e = (size_t)dstq * 4;
    __half2 H0, L0, H1, L1;
    split2(v.x, v.y, H0, L0);
    split2(v.z, v.w, H1, L1);
    *reinterpret_cast<__half2*>(chi + e)     = H0;
    *reinterpret_cast<__half2*>(chi + e + 2) = H1;
    *reinterpret_cast<__half2*>(clo + e)     = L0;
    *reinterpret_cast<__half2*>(clo + e + 2) = L1;
}

extern "C" void kernel_launch(void* const* d_in, const int* in_sizes, int n_in,
                              void* d_out, int out_size)
{
    (void)in_sizes; (void)n_in; (void)out_size;
    const float* input   = (const float*)d_in[0];   // [B,T,D]
    const float* context = (const float*)d_in[1];   // [B,S,D]
    const float* W_in    = (const float*)d_in[2];   // [D,D]
    const float* W_out   = (const float*)d_in[3];   // [D,2D]

    float* out    = (float*)d_out;
    float* attn   = out;                                   // [T,B,D]
    float* alignv = out + (long long)TD * BD * DD;         // [T,B,S]
    float* concat = alignv + (long long)TD * BD * SD;      // [T,B,2D]

    h16 *in_hi, *in_lo, *ctx_hi, *ctx_lo, *ctxT_hi, *ctxT_lo;
    h16 *win_hi, *win_lo, *wout_hi, *wout_lo;
    h16 *h_hi, *h_lo, *av_hi, *av_lo, *cc_hi, *cc_lo;
    cudaGetSymbolAddress((void**)&in_hi,  g_in_hi);   cudaGetSymbolAddress((void**)&in_lo,  g_in_lo);
    cudaGetSymbolAddress((void**)&ctx_hi, g_ctx_hi);  cudaGetSymbolAddress((void**)&ctx_lo, g_ctx_lo);
    cudaGetSymbolAddress((void**)&ctxT_hi,g_ctxT_hi); cudaGetSymbolAddress((void**)&ctxT_lo,g_ctxT_lo);
    cudaGetSymbolAddress((void**)&win_hi, g_win_hi);  cudaGetSymbolAddress((void**)&win_lo, g_win_lo);
    cudaGetSymbolAddress((void**)&wout_hi,g_wout_hi); cudaGetSymbolAddress((void**)&wout_lo,g_wout_lo);
    cudaGetSymbolAddress((void**)&h_hi,   g_h_hi);    cudaGetSymbolAddress((void**)&h_lo,   g_h_lo);
    cudaGetSymbolAddress((void**)&av_hi,  g_av_hi);   cudaGetSymbolAddress((void**)&av_lo,  g_av_lo);
    cudaGetSymbolAddress((void**)&cc_hi,  g_cc_hi);   cudaGetSymbolAddress((void**)&cc_lo,  g_cc_lo);

    cudaFuncSetAttribute(gemm_hmma<3, false, false, true>,
                         cudaFuncAttributeMaxDynamicSharedMemorySize, SMEM_TOT);
    cudaFuncSetAttribute(gemm_hmma<3, true, false, false>,
                         cudaFuncAttributeMaxDynamicSharedMemorySize, SMEM_TOT);
    cudaFuncSetAttribute(gemm_hmma<2, true, false, true>,
                         cudaFuncAttributeMaxDynamicSharedMemorySize, SMEM_TOT);
    cudaFuncSetAttribute(gemm_hmma<2, true, true, false>,
                         cudaFuncAttributeMaxDynamicSharedMemorySize, SMEM_TOT);

    // operand conversions
    split_kernel<<<(BD * TD * DD) / 1024, 256>>>(input,   in_hi,  in_lo,  (long long)BD * TD * DD);
    split_kernel<<<(BD * SD * DD) / 1024, 256>>>(context, ctx_hi, ctx_lo, (long long)BD * SD * DD);
    split_kernel<<<(DD * DD) / 1024, 256>>>(W_in,  win_hi,  win_lo,  (long long)DD * DD);
    split_kernel<<<(DD * 2 * DD) / 1024, 256>>>(W_out, wout_hi, wout_lo, (long long)DD * 2 * DD);
    transpose_split_kernel<<<dim3(DD / 32, SD / 32, BD), 256>>>(context, ctxT_hi, ctxT_lo);

    // 1) h = input @ W_in^T : [16384,1024], K=1024 -> fp16 pair out  (3-term: feeds logits)
    gemm_hmma<3, false, false, true><<<dim3(DD / 128, (BD * TD) / 128, 1), 256, SMEM_TOT>>>(
        in_hi, in_lo, DD, 0LL, win_hi, win_lo, DD, 0LL,
        nullptr, 0LL, 0LL, h_hi, h_lo, DD, 0LL, DD);

    // 2) align[b] = h[b] @ ctx[b]^T : K=1024 -> fp32 into [T,B,S]  (3-term: logits)
    gemm_hmma<3, true, false, false><<<dim3(SD / 128, TD / 128, BD), 256, SMEM_TOT>>>(
        h_hi, h_lo, DD, (long long)TD * DD, ctx_hi, ctx_lo, DD, (long long)SD * DD,
        alignv, (long long)BD * SD, (long long)SD, nullptr, nullptr, 0LL, 0LL, DD);

    // 3) softmax over S + fp16 pair
    softmax1024<<<TD * BD, 256>>>(alignv, av_hi, av_lo);

    // 4) input -> concat second half (fp32 + pair)
    copy_input_to_concat<<<(BD * TD * DD / 4) / 256, 256>>>(input, concat, cc_hi, cc_lo);

    // 5) c[b] = av[b] @ ctxT[b]^T : K=1024(S) -> fp32 + pair  (2-term: ~1e-4 rel)
    gemm_hmma<2, true, false, true><<<dim3(DD / 128, TD / 128, BD), 256, SMEM_TOT>>>(
        av_hi, av_lo, (long long)BD * SD, (long long)SD,
        ctxT_hi, ctxT_lo, SD, (long long)DD * SD,
        concat, (long long)BD * 2 * DD, (long long)(2 * DD),
        cc_hi, cc_lo, (long long)BD * 2 * DD, (long long)(2 * DD), SD);

    // 6) attn = tanh(concat @ W_out^T) : K=2048 -> fp32  (2-term: ~1e-4 pre-tanh)
    gemm_hmma<2, true, true, false><<<dim3(DD / 128, (TD * BD) / 128, 1), 256, SMEM_TOT>>>(
        cc_hi, cc_lo, 2 * DD, 0LL, wout_hi, wout_lo, 2 * DD, 0LL,
        attn, DD, 0LL, nullptr, nullptr, 0LL, 0LL, 2 * DD);
}

// round 8
// speedup vs baseline: 3.0065x; 1.0409x over previous
#include <cuda_runtime.h>
#include <cuda_fp16.h>
#include <cstdint>
#include <math.h>

#define BD 32
#define TD 512
#define SD 1024
#define DD 1024

typedef __half h16;

// ---------------- scratch (device globals; no runtime allocation) ----------------
__device__ h16 g_in_hi [(size_t)BD*TD*DD],   g_in_lo [(size_t)BD*TD*DD];
__device__ h16 g_ctx_hi[(size_t)BD*SD*DD],   g_ctx_lo[(size_t)BD*SD*DD];
__device__ h16 g_ctxT_hi[(size_t)BD*DD*SD],  g_ctxT_lo[(size_t)BD*DD*SD];
__device__ h16 g_win_hi[(size_t)DD*DD],      g_win_lo[(size_t)DD*DD];
__device__ h16 g_wout_hi[(size_t)DD*2*DD],   g_wout_lo[(size_t)DD*2*DD];
__device__ h16 g_h_hi  [(size_t)BD*TD*DD],   g_h_lo  [(size_t)BD*TD*DD];
__device__ h16 g_av_hi [(size_t)TD*BD*SD],   g_av_lo [(size_t)TD*BD*SD];
__device__ h16 g_cc_hi [(size_t)TD*BD*2*DD], g_cc_lo [(size_t)TD*BD*2*DD];

// ---------------- PTX helpers ----------------
__device__ __forceinline__ uint32_t smem_u32(const void* p) {
    uint32_t a;
    asm("{ .reg .u64 t; cvta.to.shared.u64 t, %1; cvt.u32.u64 %0, t; }" : "=r"(a) : "l"(p));
    return a;
}
__device__ __forceinline__ void cp16(uint32_t dst, const void* src) {
    asm volatile("cp.async.cg.shared.global [%0], [%1], 16;\n" :: "r"(dst), "l"(src) : "memory");
}
#define CP_COMMIT() asm volatile("cp.async.commit_group;\n" ::: "memory")
#define CP_WAIT(n)  asm volatile("cp.async.wait_group %0;\n" :: "n"(n) : "memory")
#define SW128(o)    ((o) ^ (((o) >> 3) & 0x70))

__device__ __forceinline__ void ldsm4(uint32_t* r, uint32_t addr) {
    asm volatile("ldmatrix.sync.aligned.m8n8.x4.shared.b16 {%0,%1,%2,%3}, [%4];"
                 : "=r"(r[0]), "=r"(r[1]), "=r"(r[2]), "=r"(r[3]) : "r"(addr));
}
__device__ __forceinline__ void mma16816(float* c, const uint32_t* a, const uint32_t* b) {
    asm volatile(
        "mma.sync.aligned.m16n8k16.row.col.f32.f16.f16.f32 "
        "{%0,%1,%2,%3}, {%4,%5,%6,%7}, {%8,%9}, {%0,%1,%2,%3};"
        : "+f"(c[0]), "+f"(c[1]), "+f"(c[2]), "+f"(c[3])
        : "r"(a[0]), "r"(a[1]), "r"(a[2]), "r"(a[3]), "r"(b[0]), "r"(b[1]));
}
__device__ __forceinline__ void split2(float a, float b, __half2& H, __half2& L) {
    __half ha = __float2half_rn(a), hb = __float2half_rn(b);
    H = __halves2half2(ha, hb);
    L = __halves2half2(__float2half_rn(a - __half2float(ha)),
                       __float2half_rn(b - __half2float(hb)));
}

// ---------------- fp16-split HMMA GEMM, occupancy-2, single-sync mainloop ----------------
// C[m,n] = sum_k A[m,k]*B[n,k] (NT). A,B fp16 (hi,lo) pairs of fp32.
// CTA 128x128, warp tile 64x32 (8 warps as 2Mx4N). K-chunk 32 with hi|lo packed
// per 128B row -> stage 32KB; 3-stage cp.async pipeline; 2 CTAs/SM.
static constexpr int ST_BYTES = 32768;           // A 16K (hi|lo packed) + B 16K
static constexpr int SMEM_TOT = 3 * ST_BYTES;    // 96 KB -> 2 CTAs/SM

template <int TERMS, int K, bool WF32, bool WTANH, bool WPAIR>
__global__ void __launch_bounds__(256, 2) gemm_hmma(
    const h16* __restrict__ Ahi_, const h16* __restrict__ Alo_,
    long long lda, long long sA,
    const h16* __restrict__ Bhi_, const h16* __restrict__ Blo_,
    long long ldb, long long sB,
    float* __restrict__ C_, long long ldc, long long sC,
    h16* __restrict__ Phi_, h16* __restrict__ Plo_,
    long long ldp, long long sP)
{
    extern __shared__ char smem[];
    const uint32_t sb = smem_u32(smem);
    const int tid = threadIdx.x, wid = tid >> 5, l = tid & 31;
    const long long bz = blockIdx.z;
    const h16* Ahi = Ahi_ + bz * sA;
    const h16* Alo = Alo_ + bz * sA;
    const h16* Bhi = Bhi_ + bz * sB;
    const h16* Blo = Blo_ + bz * sB;
    const long long m0 = (long long)blockIdx.y * 128;
    const long long n0 = (long long)blockIdx.x * 128;

    const int wm = wid & 1;        // 2 M groups of 64
    const int wn = wid >> 1;       // 4 N groups of 32

    // ldmatrix lane byte offsets within a 128B-row tile
    // A (m16k16): bit3 -> +8 rows, bit4 -> +16B k-chunk
    const int laneA = ((l & 7) + ((l >> 3) & 1) * 8) * 128 + ((l >> 4) & 1) * 16;
    // B (n16k16): bit4 -> +8 rows, bit3 -> +16B k-chunk
    const int laneB = ((l & 7) + ((l >> 4) & 1) * 8) * 128 + ((l >> 3) & 1) * 16;

    float acc[4][4][4];
#pragma unroll
    for (int i = 0; i < 4; i++)
#pragma unroll
        for (int j = 0; j < 4; j++)
#pragma unroll
            for (int v = 0; v < 4; v++) acc[i][j][v] = 0.f;

    // row layout: [32 hi fp16 | 32 lo fp16] = 128B, SW128 swizzled
    auto load_chunk = [&](int stage, int kt) {
        const long long k0 = (long long)kt << 5;
        const uint32_t st = sb + stage * ST_BYTES;
#pragma unroll
        for (int i = 0; i < 4; i++) {            // A: 1024 16B chunks
            int ch = tid + (i << 8);
            int r = ch >> 3, c = ch & 7;
            const h16* base = (c < 4) ? Ahi : Alo;
            cp16(st + SW128(r * 128 + c * 16),
                 base + (m0 + r) * lda + k0 + (c & 3) * 8);
        }
#pragma unroll
        for (int i = 0; i < 4; i++) {            // B: 1024 16B chunks
            int ch = tid + (i << 8);
            int r = ch >> 3, c = ch & 7;
            const h16* base = (c < 4) ? Bhi : Blo;
            cp16(st + 16384 + SW128(r * 128 + c * 16),
                 base + (n0 + r) * ldb + k0 + (c & 3) * 8);
        }
        CP_COMMIT();
    };

    constexpr int KT = K >> 5;
    load_chunk(0, 0);
    load_chunk(1, 1);
    int s = 0, ls = 2;
#pragma unroll 1
    for (int kt = 0; kt < KT; kt++) {
        // wait for chunk kt's data (all but the most recent group), then ONE barrier
        if (kt + 1 < KT) { CP_WAIT(1); } else { CP_WAIT(0); }
        __syncthreads();
        // issue next load AFTER the barrier: stage (kt+2)%3 == stage (kt-1)%3,
        // which all warps have finished reading (barrier just retired compute kt-1)
        if (kt + 2 < KT) {
            load_chunk(ls, kt + 2);
            ls = (ls == 2) ? 0 : ls + 1;
        }

        const uint32_t aB = sb + s * ST_BYTES;
        const uint32_t bB = aB + 16384;
#pragma unroll
        for (int kk = 0; kk < 2; kk++) {
            uint32_t Bh[2][4], Bl[2][4];
#pragma unroll
            for (int pt = 0; pt < 2; pt++) {
                int off = (wn * 32 + pt * 16) * 128 + kk * 32 + laneB;
                ldsm4(Bh[pt], bB + SW128(off));        // hi half of row
                ldsm4(Bl[pt], bB + SW128(off + 64));   // lo half of row
            }
#pragma unroll
            for (int mt = 0; mt < 4; mt++) {
                int offA = (wm * 64 + mt * 16) * 128 + kk * 32 + laneA;
                uint32_t Ah[4];
                ldsm4(Ah, aB + SW128(offA));
#pragma unroll
                for (int j = 0; j < 4; j++) {
                    float* c = acc[mt][j];
                    mma16816(c, Ah, &Bh[j >> 1][(j & 1) * 2]);
                    mma16816(c, Ah, &Bl[j >> 1][(j & 1) * 2]);
                }
                if (TERMS == 3) {
                    uint32_t Al[4];
                    ldsm4(Al, aB + SW128(offA + 64));
#pragma unroll
                    for (int j = 0; j < 4; j++)
                        mma16816(acc[mt][j], Al, &Bh[j >> 1][(j & 1) * 2]);
                }
            }
        }
        s = (s == 2) ? 0 : s + 1;
    }

    // ---------------- epilogue ----------------
    float* C = C_ + bz * sC;
    h16* Ph = Phi_ + bz * sP;
    h16* Pl = Plo_ + bz * sP;
    const int q = l >> 2, tl = l & 3;
#pragma unroll
    for (int mt = 0; mt < 4; mt++) {
#pragma unroll
        for (int nt = 0; nt < 4; nt++) {
            long long r0 = m0 + wm * 64 + mt * 16 + q;
            long long col = n0 + wn * 32 + nt * 8 + tl * 2;
            float d0 = acc[mt][nt][0], d1 = acc[mt][nt][1];
            float d2 = acc[mt][nt][2], d3 = acc[mt][nt][3];
            if (WTANH) { d0 = tanhf(d0); d1 = tanhf(d1); d2 = tanhf(d2); d3 = tanhf(d3); }
            if (WF32) {
                *reinterpret_cast<float2*>(C + r0 * ldc + col)       = make_float2(d0, d1);
                *reinterpret_cast<float2*>(C + (r0 + 8) * ldc + col) = make_float2(d2, d3);
            }
            if (WPAIR) {
                __half2 H, L;
                split2(d0, d1, H, L);
                *reinterpret_cast<__half2*>(Ph + r0 * ldp + col) = H;
                *reinterpret_cast<__half2*>(Pl + r0 * ldp + col) = L;
                split2(d2, d3, H, L);
                *reinterpret_cast<__half2*>(Ph + (r0 + 8) * ldp + col) = H;
                *reinterpret_cast<__half2*>(Pl + (r0 + 8) * ldp + col) = L;
            }
        }
    }
}

// ---------------- fp32 -> (hi,lo) fp16 split ----------------
__global__ void __launch_bounds__(256) split_kernel(const float* __restrict__ src,
                                                    h16* __restrict__ hi,
                                                    h16* __restrict__ lo, long long n)
{
    long long i4 = ((long long)blockIdx.x * 256 + threadIdx.x) * 4;
    if (i4 >= n) return;
    float4 v = *reinterpret_cast<const float4*>(src + i4);
    __half2 H0, L0, H1, L1;
    split2(v.x, v.y, H0, L0);
    split2(v.z, v.w, H1, L1);
    *reinterpret_cast<__half2*>(hi + i4)     = H0;
    *reinterpret_cast<__half2*>(hi + i4 + 2) = H1;
    *reinterpret_cast<__half2*>(lo + i4)     = L0;
    *reinterpret_cast<__half2*>(lo + i4 + 2) = L1;
}

// ------ fused: input split (for GEMM1) + input -> concat_c[t,b,D+d] (fp32 + pair) ------
__global__ void __launch_bounds__(256) input_prep_kernel(const float* __restrict__ in,
                                                         h16* __restrict__ ihi,
                                                         h16* __restrict__ ilo,
                                                         float* __restrict__ concat,
                                                         h16* __restrict__ chi,
                                                         h16* __restrict__ clo)
{
    const long long DQ = DD / 4;
    long long g = (long long)blockIdx.x * blockDim.x + threadIdx.x;
    long long b   = g / (TD * DQ);
    long long rem = g - b * (TD * DQ);
    long long t   = rem / DQ;
    long long dq  = rem - t * DQ;
    float4 v = reinterpret_cast<const float4*>(in)[g];

    __half2 H0, L0, H1, L1;
    split2(v.x, v.y, H0, L0);
    split2(v.z, v.w, H1, L1);

    const size_t si = (size_t)g * 4;  // [B,T,D] layout
    *reinterpret_cast<__half2*>(ihi + si)     = H0;
    *reinterpret_cast<__half2*>(ihi + si + 2) = H1;
    *reinterpret_cast<__half2*>(ilo + si)     = L0;
    *reinterpret_cast<__half2*>(ilo + si + 2) = L1;

    long long dstq = ((t * BD + b) * (2 * DD) + DD) / 4 + dq;
    reinterpret_cast<float4*>(concat)[dstq] = v;
    const size_t e = (size_t)dstq * 4;
    *reinterpret_cast<__half2*>(chi + e)     = H0;
    *reinterpret_cast<__half2*>(chi + e + 2) = H1;
    *reinterpret_cast<__half2*>(clo + e)     = L0;
    *reinterpret_cast<__half2*>(clo + e + 2) = L1;
}

// -------- context transpose + split: ctxT[b,d,s] = ctx[b,s,d] --------
__global__ void __launch_bounds__(256) transpose_split_kernel(const float* __restrict__ ctx,
                                                              h16* __restrict__ tHi,
                                                              h16* __restrict__ tLo)
{
    __shared__ float tile[32][33];
    const int b = blockIdx.z;
    const int d0 = blockIdx.x * 32, s0 = blockIdx.y * 32;
    const int tx = threadIdx.x & 31, ty = threadIdx.x >> 5;
    const float* src = ctx + (size_t)b * SD * DD;
#pragma unroll
    for (int j = 0; j < 4; j++)
        tile[ty + j * 8][tx] = src[(size_t)(s0 + ty + j * 8) * DD + d0 + tx];
    __syncthreads();
    h16* dh = tHi + (size_t)b * DD * SD;
    h16* dl = tLo + (size_t)b * DD * SD;
#pragma unroll
    for (int j = 0; j < 4; j++) {
        float v = tile[tx][ty + j * 8];
        __half h = __float2half_rn(v);
        dh[(size_t)(d0 + ty + j * 8) * SD + s0 + tx] = h;
        dl[(size_t)(d0 + ty + j * 8) * SD + s0 + tx] =
            __float2half_rn(v - __half2float(h));
    }
}

// ---------------- softmax (rows of 1024) + fp16-pair emit ----------------
__global__ void __launch_bounds__(256) softmax1024(float* __restrict__ p,
                                                   h16* __restrict__ hi,
                                                   h16* __restrict__ lo)
{
    __shared__ float red[8];
    const long long row = blockIdx.x;
    float* r = p + row * 1024;
    const int tid = threadIdx.x;
    float4 v = reinterpret_cast<float4*>(r)[tid];

    float m = fmaxf(fmaxf(v.x, v.y), fmaxf(v.z, v.w));
#pragma unroll
    for (int o = 16; o > 0; o >>= 1) m = fmaxf(m, __shfl_xor_sync(0xffffffffu, m, o));
    if ((tid & 31) == 0) red[tid >> 5] = m;
    __syncthreads();
    float bm = red[0];
#pragma unroll
    for (int i = 1; i < 8; i++) bm = fmaxf(bm, red[i]);
    __syncthreads();

    v.x = __expf(v.x - bm); v.y = __expf(v.y - bm);
    v.z = __expf(v.z - bm); v.w = __expf(v.w - bm);
    float s = v.x + v.y + v.z + v.w;
#pragma unroll
    for (int o = 16; o > 0; o >>= 1) s += __shfl_xor_sync(0xffffffffu, s, o);
    if ((tid & 31) == 0) red[tid >> 5] = s;
    __syncthreads();
    float bs = 0.f;
#pragma unroll
    for (int i = 0; i < 8; i++) bs += red[i];
    const float inv = 1.0f / bs;
    v.x *= inv; v.y *= inv; v.z *= inv; v.w *= inv;
    reinterpret_cast<float4*>(r)[tid] = v;

    const size_t off = (size_t)row * 1024 + tid * 4;
    __half2 H0, L0, H1, L1;
    split2(v.x, v.y, H0, L0);
    split2(v.z, v.w, H1, L1);
    *reinterpret_cast<__half2*>(hi + off)     = H0;
    *reinterpret_cast<__half2*>(hi + off + 2) = H1;
    *reinterpret_cast<__half2*>(lo + off)     = L0;
    *reinterpret_cast<__half2*>(lo + off + 2) = L1;
}

extern "C" void kernel_launch(void* const* d_in, const int* in_sizes, int n_in,
                              void* d_out, int out_size)
{
    (void)in_sizes; (void)n_in; (void)out_size;
    const float* input   = (const float*)d_in[0];   // [B,T,D]
    const float* context = (const float*)d_in[1];   // [B,S,D]
    const float* W_in    = (const float*)d_in[2];   // [D,D]
    const float* W_out   = (const float*)d_in[3];   // [D,2D]

    float* out    = (float*)d_out;
    float* attn   = out;                                   // [T,B,D]
    float* alignv = out + (long long)TD * BD * DD;         // [T,B,S]
    float* concat = alignv + (long long)TD * BD * SD;      // [T,B,2D]

    h16 *in_hi, *in_lo, *ctx_hi, *ctx_lo, *ctxT_hi, *ctxT_lo;
    h16 *win_hi, *win_lo, *wout_hi, *wout_lo;
    h16 *h_hi, *h_lo, *av_hi, *av_lo, *cc_hi, *cc_lo;
    cudaGetSymbolAddress((void**)&in_hi,  g_in_hi);   cudaGetSymbolAddress((void**)&in_lo,  g_in_lo);
    cudaGetSymbolAddress((void**)&ctx_hi, g_ctx_hi);  cudaGetSymbolAddress((void**)&ctx_lo, g_ctx_lo);
    cudaGetSymbolAddress((void**)&ctxT_hi,g_ctxT_hi); cudaGetSymbolAddress((void**)&ctxT_lo,g_ctxT_lo);
    cudaGetSymbolAddress((void**)&win_hi, g_win_hi);  cudaGetSymbolAddress((void**)&win_lo, g_win_lo);
    cudaGetSymbolAddress((void**)&wout_hi,g_wout_hi); cudaGetSymbolAddress((void**)&wout_lo,g_wout_lo);
    cudaGetSymbolAddress((void**)&h_hi,   g_h_hi);    cudaGetSymbolAddress((void**)&h_lo,   g_h_lo);
    cudaGetSymbolAddress((void**)&av_hi,  g_av_hi);   cudaGetSymbolAddress((void**)&av_lo,  g_av_lo);
    cudaGetSymbolAddress((void**)&cc_hi,  g_cc_hi);   cudaGetSymbolAddress((void**)&cc_lo,  g_cc_lo);

    cudaFuncSetAttribute(gemm_hmma<3, 1024, false, false, true>,
                         cudaFuncAttributeMaxDynamicSharedMemorySize, SMEM_TOT);
    cudaFuncSetAttribute(gemm_hmma<3, 1024, true, false, false>,
                         cudaFuncAttributeMaxDynamicSharedMemorySize, SMEM_TOT);
    cudaFuncSetAttribute(gemm_hmma<2, 1024, true, false, true>,
                         cudaFuncAttributeMaxDynamicSharedMemorySize, SMEM_TOT);
    cudaFuncSetAttribute(gemm_hmma<2, 2048, true, true, false>,
                         cudaFuncAttributeMaxDynamicSharedMemorySize, SMEM_TOT);

    // operand conversions
    input_prep_kernel<<<(BD * TD * DD / 4) / 256, 256>>>(input, in_hi, in_lo,
                                                         concat, cc_hi, cc_lo);
    split_kernel<<<(BD * SD * DD) / 1024, 256>>>(context, ctx_hi, ctx_lo, (long long)BD * SD * DD);
    split_kernel<<<(DD * DD) / 1024, 256>>>(W_in,  win_hi,  win_lo,  (long long)DD * DD);
    split_kernel<<<(DD * 2 * DD) / 1024, 256>>>(W_out, wout_hi, wout_lo, (long long)DD * 2 * DD);
    transpose_split_kernel<<<dim3(DD / 32, SD / 32, BD), 256>>>(context, ctxT_hi, ctxT_lo);

    // 1) h = input @ W_in^T : [16384,1024], K=1024 -> fp16 pair out  (3-term: feeds logits)
    gemm_hmma<3, 1024, false, false, true><<<dim3(DD / 128, (BD * TD) / 128, 1), 256, SMEM_TOT>>>(
        in_hi, in_lo, DD, 0LL, win_hi, win_lo, DD, 0LL,
        nullptr, 0LL, 0LL, h_hi, h_lo, DD, 0LL);

    // 2) align[b] = h[b] @ ctx[b]^T : K=1024 -> fp32 into [T,B,S]  (3-term: logits)
    gemm_hmma<3, 1024, true, false, false><<<dim3(SD / 128, TD / 128, BD), 256, SMEM_TOT>>>(
        h_hi, h_lo, DD, (long long)TD * DD, ctx_hi, ctx_lo, DD, (long long)SD * DD,
        alignv, (long long)BD * SD, (long long)SD, nullptr, nullptr, 0LL, 0LL);

    // 3) softmax over S + fp16 pair
    softmax1024<<<TD * BD, 256>>>(alignv, av_hi, av_lo);

    // 4) c[b] = av[b] @ ctxT[b]^T : K=1024(S) -> fp32 + pair  (2-term: ~1e-4 rel)
    gemm_hmma<2, 1024, true, false, true><<<dim3(DD / 128, TD / 128, BD), 256, SMEM_TOT>>>(
        av_hi, av_lo, (long long)BD * SD, (long long)SD,
        ctxT_hi, ctxT_lo, SD, (long long)DD * SD,
        concat, (long long)BD * 2 * DD, (long long)(2 * DD),
        cc_hi, cc_lo, (long long)BD * 2 * DD, (long long)(2 * DD));

    // 5) attn = tanh(concat @ W_out^T) : K=2048 -> fp32  (2-term: ~1e-4 pre-tanh)
    gemm_hmma<2, 2048, true, true, false><<<dim3(DD / 128, (TD * BD) / 128, 1), 256, SMEM_TOT>>>(
        cc_hi, cc_lo, 2 * DD, 0LL, wout_hi, wout_lo, 2 * DD, 0LL,
        attn, DD, 0LL, nullptr, nullptr, 0LL, 0LL);
}

// round 10
// speedup vs baseline: 3.1266x; 1.0399x over previous
#include <cuda_runtime.h>
#include <cuda_fp16.h>
#include <cstdint>
#include <math.h>

#define BD 32
#define TD 512
#define SD 1024
#define DD 1024

typedef __half h16;

// ---------------- scratch (device globals; no runtime allocation) ----------------
__device__ h16 g_in_hi [(size_t)BD*TD*DD],   g_in_lo [(size_t)BD*TD*DD];
__device__ h16 g_ctx_hi[(size_t)BD*SD*DD],   g_ctx_lo[(size_t)BD*SD*DD];
__device__ h16 g_ctxT_hi[(size_t)BD*DD*SD],  g_ctxT_lo[(size_t)BD*DD*SD];
__device__ h16 g_win_hi[(size_t)DD*DD],      g_win_lo[(size_t)DD*DD];
__device__ h16 g_wout_hi[(size_t)DD*2*DD],   g_wout_lo[(size_t)DD*2*DD];
__device__ h16 g_h_hi  [(size_t)BD*TD*DD],   g_h_lo  [(size_t)BD*TD*DD];
__device__ h16 g_av_hi [(size_t)TD*BD*SD],   g_av_lo [(size_t)TD*BD*SD];
__device__ h16 g_cc_hi [(size_t)TD*BD*2*DD], g_cc_lo [(size_t)TD*BD*2*DD];
__device__ float g_cbuf[(size_t)TD*BD*DD];   // GEMM6a partial (input @ Wout_i^T)

// ---------------- PTX helpers ----------------
__device__ __forceinline__ uint32_t smem_u32(const void* p) {
    uint32_t a;
    asm("{ .reg .u64 t; cvta.to.shared.u64 t, %1; cvt.u32.u64 %0, t; }" : "=r"(a) : "l"(p));
    return a;
}
__device__ __forceinline__ void cp16(uint32_t dst, const void* src) {
    asm volatile("cp.async.cg.shared.global [%0], [%1], 16;\n" :: "r"(dst), "l"(src) : "memory");
}
#define CP_COMMIT() asm volatile("cp.async.commit_group;\n" ::: "memory")
#define CP_WAIT(n)  asm volatile("cp.async.wait_group %0;\n" :: "n"(n) : "memory")
#define SW128(o)    ((o) ^ (((o) >> 3) & 0x70))

__device__ __forceinline__ void ldsm4(uint32_t* r, uint32_t addr) {
    asm volatile("ldmatrix.sync.aligned.m8n8.x4.shared.b16 {%0,%1,%2,%3}, [%4];"
                 : "=r"(r[0]), "=r"(r[1]), "=r"(r[2]), "=r"(r[3]) : "r"(addr));
}
__device__ __forceinline__ void mma16816(float* c, const uint32_t* a, const uint32_t* b) {
    asm volatile(
        "mma.sync.aligned.m16n8k16.row.col.f32.f16.f16.f32 "
        "{%0,%1,%2,%3}, {%4,%5,%6,%7}, {%8,%9}, {%0,%1,%2,%3};"
        : "+f"(c[0]), "+f"(c[1]), "+f"(c[2]), "+f"(c[3])
        : "r"(a[0]), "r"(a[1]), "r"(a[2]), "r"(a[3]), "r"(b[0]), "r"(b[1]));
}
__device__ __forceinline__ void split2(float a, float b, __half2& H, __half2& L) {
    __half ha = __float2half_rn(a), hb = __float2half_rn(b);
    H = __halves2half2(ha, hb);
    L = __halves2half2(__float2half_rn(a - __half2float(ha)),
                       __float2half_rn(b - __half2float(hb)));
}

// ---------------- fp16-split HMMA GEMM, occupancy-2, single-sync mainloop ----------------
// C[m,n] = sum_k A[m,k]*B[n,k] (NT). A,B fp16 (hi,lo) pairs of fp32.
// CTA 128x128, warp tile 64x32 (8 warps as 2Mx4N). K-chunk 32 with hi|lo packed
// per 128B row -> stage 32KB; 3-stage cp.async pipeline; 2 CTAs/SM.
// LOADC: initialize accumulators from Cin (fp32) instead of zero.
static constexpr int ST_BYTES = 32768;           // A 16K (hi|lo packed) + B 16K
static constexpr int SMEM_TOT = 3 * ST_BYTES;    // 96 KB -> 2 CTAs/SM

template <int TERMS, int K, bool WF32, bool WTANH, bool WPAIR, bool LOADC>
__global__ void __launch_bounds__(256, 2) gemm_hmma(
    const h16* __restrict__ Ahi_, const h16* __restrict__ Alo_,
    long long lda, long long sA,
    const h16* __restrict__ Bhi_, const h16* __restrict__ Blo_,
    long long ldb, long long sB,
    float* __restrict__ C_, long long ldc, long long sC,
    h16* __restrict__ Phi_, h16* __restrict__ Plo_,
    long long ldp, long long sP,
    const float* __restrict__ Cin_)
{
    extern __shared__ char smem[];
    const uint32_t sb = smem_u32(smem);
    const int tid = threadIdx.x, wid = tid >> 5, l = tid & 31;
    const long long bz = blockIdx.z;
    const h16* Ahi = Ahi_ + bz * sA;
    const h16* Alo = Alo_ + bz * sA;
    const h16* Bhi = Bhi_ + bz * sB;
    const h16* Blo = Blo_ + bz * sB;
    const long long m0 = (long long)blockIdx.y * 128;
    const long long n0 = (long long)blockIdx.x * 128;

    const int wm = wid & 1;        // 2 M groups of 64
    const int wn = wid >> 1;       // 4 N groups of 32
    const int q = l >> 2, tl = l & 3;

    // ldmatrix lane byte offsets within a 128B-row tile
    // A (m16k16): bit3 -> +8 rows, bit4 -> +16B k-chunk
    const int laneA = ((l & 7) + ((l >> 3) & 1) * 8) * 128 + ((l >> 4) & 1) * 16;
    // B (n16k16): bit4 -> +8 rows, bit3 -> +16B k-chunk
    const int laneB = ((l & 7) + ((l >> 4) & 1) * 8) * 128 + ((l >> 3) & 1) * 16;

    float acc[4][4][4];
    if (LOADC) {
#pragma unroll
        for (int mt = 0; mt < 4; mt++)
#pragma unroll
            for (int nt = 0; nt < 4; nt++) {
                long long r0 = m0 + wm * 64 + mt * 16 + q;
                long long col = n0 + wn * 32 + nt * 8 + tl * 2;
                float2 u0 = *reinterpret_cast<const float2*>(Cin_ + r0 * ldc + col);
                float2 u1 = *reinterpret_cast<const float2*>(Cin_ + (r0 + 8) * ldc + col);
                acc[mt][nt][0] = u0.x; acc[mt][nt][1] = u0.y;
                acc[mt][nt][2] = u1.x; acc[mt][nt][3] = u1.y;
            }
    } else {
#pragma unroll
        for (int i = 0; i < 4; i++)
#pragma unroll
            for (int j = 0; j < 4; j++)
#pragma unroll
                for (int v = 0; v < 4; v++) acc[i][j][v] = 0.f;
    }

    // row layout: [32 hi fp16 | 32 lo fp16] = 128B, SW128 swizzled
    auto load_chunk = [&](int stage, int kt) {
        const long long k0 = (long long)kt << 5;
        const uint32_t st = sb + stage * ST_BYTES;
#pragma unroll
        for (int i = 0; i < 4; i++) {            // A: 1024 16B chunks
            int ch = tid + (i << 8);
            int r = ch >> 3, c = ch & 7;
            const h16* base = (c < 4) ? Ahi : Alo;
            cp16(st + SW128(r * 128 + c * 16),
                 base + (m0 + r) * lda + k0 + (c & 3) * 8);
        }
#pragma unroll
        for (int i = 0; i < 4; i++) {            // B: 1024 16B chunks
            int ch = tid + (i << 8);
            int r = ch >> 3, c = ch & 7;
            const h16* base = (c < 4) ? Bhi : Blo;
            cp16(st + 16384 + SW128(r * 128 + c * 16),
                 base + (n0 + r) * ldb + k0 + (c & 3) * 8);
        }
        CP_COMMIT();
    };

    constexpr int KT = K >> 5;
    load_chunk(0, 0);
    load_chunk(1, 1);
    int s = 0, ls = 2;
#pragma unroll 1
    for (int kt = 0; kt < KT; kt++) {
        // wait for chunk kt's data, then ONE barrier
        if (kt + 1 < KT) { CP_WAIT(1); } else { CP_WAIT(0); }
        __syncthreads();
        // issue next load AFTER the barrier: stage (kt+2)%3 == stage (kt-1)%3
        if (kt + 2 < KT) {
            load_chunk(ls, kt + 2);
            ls = (ls == 2) ? 0 : ls + 1;
        }

        const uint32_t aB = sb + s * ST_BYTES;
        const uint32_t bB = aB + 16384;
#pragma unroll
        for (int kk = 0; kk < 2; kk++) {
            uint32_t Bh[2][4], Bl[2][4];
#pragma unroll
            for (int pt = 0; pt < 2; pt++) {
                int off = (wn * 32 + pt * 16) * 128 + kk * 32 + laneB;
                ldsm4(Bh[pt], bB + SW128(off));        // hi half of row
                ldsm4(Bl[pt], bB + SW128(off + 64));   // lo half of row
            }
#pragma unroll
            for (int mt = 0; mt < 4; mt++) {
                int offA = (wm * 64 + mt * 16) * 128 + kk * 32 + laneA;
                uint32_t Ah[4];
                ldsm4(Ah, aB + SW128(offA));
#pragma unroll
                for (int j = 0; j < 4; j++) {
                    float* c = acc[mt][j];
                    mma16816(c, Ah, &Bh[j >> 1][(j & 1) * 2]);
                    mma16816(c, Ah, &Bl[j >> 1][(j & 1) * 2]);
                }
                if (TERMS == 3) {
                    uint32_t Al[4];
                    ldsm4(Al, aB + SW128(offA + 64));
#pragma unroll
                    for (int j = 0; j < 4; j++)
                        mma16816(acc[mt][j], Al, &Bh[j >> 1][(j & 1) * 2]);
                }
            }
        }
        s = (s == 2) ? 0 : s + 1;
    }

    // ---------------- epilogue ----------------
    float* C = C_ + bz * sC;
    h16* Ph = Phi_ + bz * sP;
    h16* Pl = Plo_ + bz * sP;
#pragma unroll
    for (int mt = 0; mt < 4; mt++) {
#pragma unroll
        for (int nt = 0; nt < 4; nt++) {
            long long r0 = m0 + wm * 64 + mt * 16 + q;
            long long col = n0 + wn * 32 + nt * 8 + tl * 2;
            float d0 = acc[mt][nt][0], d1 = acc[mt][nt][1];
            float d2 = acc[mt][nt][2], d3 = acc[mt][nt][3];
            if (WTANH) { d0 = tanhf(d0); d1 = tanhf(d1); d2 = tanhf(d2); d3 = tanhf(d3); }
            if (WF32) {
                *reinterpret_cast<float2*>(C + r0 * ldc + col)       = make_float2(d0, d1);
                *reinterpret_cast<float2*>(C + (r0 + 8) * ldc + col) = make_float2(d2, d3);
            }
            if (WPAIR) {
                __half2 H, L;
                split2(d0, d1, H, L);
                *reinterpret_cast<__half2*>(Ph + r0 * ldp + col) = H;
                *reinterpret_cast<__half2*>(Pl + r0 * ldp + col) = L;
                split2(d2, d3, H, L);
                *reinterpret_cast<__half2*>(Ph + (r0 + 8) * ldp + col) = H;
                *reinterpret_cast<__half2*>(Pl + (r0 + 8) * ldp + col) = L;
            }
        }
    }
}

// ---------------- fp32 -> (hi,lo) fp16 split ----------------
__global__ void __launch_bounds__(256) split_kernel(const float* __restrict__ src,
                                                    h16* __restrict__ hi,
                                                    h16* __restrict__ lo, long long n)
{
    long long i4 = ((long long)blockIdx.x * 256 + threadIdx.x) * 4;
    if (i4 >= n) return;
    float4 v = *reinterpret_cast<const float4*>(src + i4);
    __half2 H0, L0, H1, L1;
    split2(v.x, v.y, H0, L0);
    split2(v.z, v.w, H1, L1);
    *reinterpret_cast<__half2*>(hi + i4)     = H0;
    *reinterpret_cast<__half2*>(hi + i4 + 2) = H1;
    *reinterpret_cast<__half2*>(lo + i4)     = L0;
    *reinterpret_cast<__half2*>(lo + i4 + 2) = L1;
}

// ------ fused: input split (for GEMM1) + input -> concat_c[t,b,D+d] (fp32 + pair) ------
__global__ void __launch_bounds__(256) input_prep_kernel(const float* __restrict__ in,
                                                         h16* __restrict__ ihi,
                                                         h16* __restrict__ ilo,
                                                         float* __restrict__ concat,
                                                         h16* __restrict__ chi,
                                                         h16* __restrict__ clo)
{
    const long long DQ = DD / 4;
    long long g = (long long)blockIdx.x * blockDim.x + threadIdx.x;
    long long b   = g / (TD * DQ);
    long long rem = g - b * (TD * DQ);
    long long t   = rem / DQ;
    long long dq  = rem - t * DQ;
    float4 v = reinterpret_cast<const float4*>(in)[g];

    __half2 H0, L0, H1, L1;
    split2(v.x, v.y, H0, L0);
    split2(v.z, v.w, H1, L1);

    const size_t si = (size_t)g * 4;  // [B,T,D] layout
    *reinterpret_cast<__half2*>(ihi + si)     = H0;
    *reinterpret_cast<__half2*>(ihi + si + 2) = H1;
    *reinterpret_cast<__half2*>(ilo + si)     = L0;
    *reinterpret_cast<__half2*>(ilo + si + 2) = L1;

    long long dstq = ((t * BD + b) * (2 * DD) + DD) / 4 + dq;
    reinterpret_cast<float4*>(concat)[dstq] = v;
    const size_t e = (size_t)dstq * 4;
    *reinterpret_cast<__half2*>(chi + e)     = H0;
    *reinterpret_cast<__half2*>(chi + e + 2) = H1;
    *reinterpret_cast<__half2*>(clo + e)     = L0;
    *reinterpret_cast<__half2*>(clo + e + 2) = L1;
}

// -------- context transpose + split: ctxT[b,d,s] = ctx[b,s,d] --------
__global__ void __launch_bounds__(256) transpose_split_kernel(const float* __restrict__ ctx,
                                                              h16* __restrict__ tHi,
                                                              h16* __restrict__ tLo)
{
    __shared__ float tile[32][33];
    const int b = blockIdx.z;
    const int d0 = blockIdx.x * 32, s0 = blockIdx.y * 32;
    const int tx = threadIdx.x & 31, ty = threadIdx.x >> 5;
    const float* src = ctx + (size_t)b * SD * DD;
#pragma unroll
    for (int j = 0; j < 4; j++)
        tile[ty + j * 8][tx] = src[(size_t)(s0 + ty + j * 8) * DD + d0 + tx];
    __syncthreads();
    h16* dh = tHi + (size_t)b * DD * SD;
    h16* dl = tLo + (size_t)b * DD * SD;
#pragma unroll
    for (int j = 0; j < 4; j++) {
        float v = tile[tx][ty + j * 8];
        __half h = __float2half_rn(v);
        dh[(size_t)(d0 + ty + j * 8) * SD + s0 + tx] = h;
        dl[(size_t)(d0 + ty + j * 8) * SD + s0 + tx] =
            __float2half_rn(v - __half2float(h));
    }
}

// ---------------- softmax (rows of 1024) + fp16-pair emit ----------------
__global__ void __launch_bounds__(256) softmax1024(float* __restrict__ p,
                                                   h16* __restrict__ hi,
                                                   h16* __restrict__ lo)
{
    __shared__ float red[8];
    const long long row = blockIdx.x;
    float* r = p + row * 1024;
    const int tid = threadIdx.x;
    float4 v = reinterpret_cast<float4*>(r)[tid];

    float m = fmaxf(fmaxf(v.x, v.y), fmaxf(v.z, v.w));
#pragma unroll
    for (int o = 16; o > 0; o >>= 1) m = fmaxf(m, __shfl_xor_sync(0xffffffffu, m, o));
    if ((tid & 31) == 0) red[tid >> 5] = m;
    __syncthreads();
    float bm = red[0];
#pragma unroll
    for (int i = 1; i < 8; i++) bm = fmaxf(bm, red[i]);
    __syncthreads();

    v.x = __expf(v.x - bm); v.y = __expf(v.y - bm);
    v.z = __expf(v.z - bm); v.w = __expf(v.w - bm);
    float s = v.x + v.y + v.z + v.w;
#pragma unroll
    for (int o = 16; o > 0; o >>= 1) s += __shfl_xor_sync(0xffffffffu, s, o);
    if ((tid & 31) == 0) red[tid >> 5] = s;
    __syncthreads();
    float bs = 0.f;
#pragma unroll
    for (int i = 0; i < 8; i++) bs += red[i];
    const float inv = 1.0f / bs;
    v.x *= inv; v.y *= inv; v.z *= inv; v.w *= inv;
    reinterpret_cast<float4*>(r)[tid] = v;

    const size_t off = (size_t)row * 1024 + tid * 4;
    __half2 H0, L0, H1, L1;
    split2(v.x, v.y, H0, L0);
    split2(v.z, v.w, H1, L1);
    *reinterpret_cast<__half2*>(hi + off)     = H0;
    *reinterpret_cast<__half2*>(hi + off + 2) = H1;
    *reinterpret_cast<__half2*>(lo + off)     = L0;
    *reinterpret_cast<__half2*>(lo + off + 2) = L1;
}

// ---------------- stream/event singletons (created at static init; no device allocs) ----------------
struct GA_Streams {
    cudaStream_t s2;
    cudaEvent_t evRoot, evIn, evCtx, ev6a;
    GA_Streams() {
        cudaStreamCreateWithFlags(&s2, cudaStreamNonBlocking);
        cudaEventCreateWithFlags(&evRoot, cudaEventDisableTiming);
        cudaEventCreateWithFlags(&evIn,   cudaEventDisableTiming);
        cudaEventCreateWithFlags(&evCtx,  cudaEventDisableTiming);
        cudaEventCreateWithFlags(&ev6a,   cudaEventDisableTiming);
    }
};
static GA_Streams g_st;

extern "C" void kernel_launch(void* const* d_in, const int* in_sizes, int n_in,
                              void* d_out, int out_size)
{
    (void)in_sizes; (void)n_in; (void)out_size;
    const float* input   = (const float*)d_in[0];   // [B,T,D]
    const float* context = (const float*)d_in[1];   // [B,S,D]
    const float* W_in    = (const float*)d_in[2];   // [D,D]
    const float* W_out   = (const float*)d_in[3];   // [D,2D]

    float* out    = (float*)d_out;
    float* attn   = out;                                   // [T,B,D]
    float* alignv = out + (long long)TD * BD * DD;         // [T,B,S]
    float* concat = alignv + (long long)TD * BD * SD;      // [T,B,2D]

    h16 *in_hi, *in_lo, *ctx_hi, *ctx_lo, *ctxT_hi, *ctxT_lo;
    h16 *win_hi, *win_lo, *wout_hi, *wout_lo;
    h16 *h_hi, *h_lo, *av_hi, *av_lo, *cc_hi, *cc_lo;
    float* cbuf;
    cudaGetSymbolAddress((void**)&in_hi,  g_in_hi);   cudaGetSymbolAddress((void**)&in_lo,  g_in_lo);
    cudaGetSymbolAddress((void**)&ctx_hi, g_ctx_hi);  cudaGetSymbolAddress((void**)&ctx_lo, g_ctx_lo);
    cudaGetSymbolAddress((void**)&ctxT_hi,g_ctxT_hi); cudaGetSymbolAddress((void**)&ctxT_lo,g_ctxT_lo);
    cudaGetSymbolAddress((void**)&win_hi, g_win_hi);  cudaGetSymbolAddress((void**)&win_lo, g_win_lo);
    cudaGetSymbolAddress((void**)&wout_hi,g_wout_hi); cudaGetSymbolAddress((void**)&wout_lo,g_wout_lo);
    cudaGetSymbolAddress((void**)&h_hi,   g_h_hi);    cudaGetSymbolAddress((void**)&h_lo,   g_h_lo);
    cudaGetSymbolAddress((void**)&av_hi,  g_av_hi);   cudaGetSymbolAddress((void**)&av_lo,  g_av_lo);
    cudaGetSymbolAddress((void**)&cc_hi,  g_cc_hi);   cudaGetSymbolAddress((void**)&cc_lo,  g_cc_lo);
    cudaGetSymbolAddress((void**)&cbuf,   g_cbuf);

    cudaFuncSetAttribute(gemm_hmma<3, 1024, false, false, true,  false>,
                         cudaFuncAttributeMaxDynamicSharedMemorySize, SMEM_TOT);
    cudaFuncSetAttribute(gemm_hmma<3, 1024, true, false, false, false>,
                         cudaFuncAttributeMaxDynamicSharedMemorySize, SMEM_TOT);
    cudaFuncSetAttribute(gemm_hmma<2, 1024, true, false, true,  false>,
                         cudaFuncAttributeMaxDynamicSharedMemorySize, SMEM_TOT);
    cudaFuncSetAttribute(gemm_hmma<2, 1024, true, false, false, false>,
                         cudaFuncAttributeMaxDynamicSharedMemorySize, SMEM_TOT);
    cudaFuncSetAttribute(gemm_hmma<2, 1024, true, true,  false, true>,
                         cudaFuncAttributeMaxDynamicSharedMemorySize, SMEM_TOT);

    cudaStream_t s2 = g_st.s2;

    // ---- fork root ----
    cudaEventRecord(g_st.evRoot, 0);
    cudaStreamWaitEvent(s2, g_st.evRoot, 0);

    // ---- main stream: input prep + win split + logit chain ----
    input_prep_kernel<<<(BD * TD * DD / 4) / 256, 256>>>(input, in_hi, in_lo,
                                                         concat, cc_hi, cc_lo);
    cudaEventRecord(g_st.evIn, 0);
    split_kernel<<<(DD * DD) / 1024, 256>>>(W_in, win_hi, win_lo, (long long)DD * DD);

    // ---- s2 branch: ctx conversions, wout split, then GEMM6a (input half) ----
    split_kernel<<<(BD * SD * DD) / 1024, 256, 0, s2>>>(context, ctx_hi, ctx_lo,
                                                        (long long)BD * SD * DD);
    split_kernel<<<(DD * 2 * DD) / 1024, 256, 0, s2>>>(W_out, wout_hi, wout_lo,
                                                       (long long)DD * 2 * DD);
    transpose_split_kernel<<<dim3(DD / 32, SD / 32, BD), 256, 0, s2>>>(context, ctxT_hi, ctxT_lo);
    cudaEventRecord(g_st.evCtx, s2);
    cudaStreamWaitEvent(s2, g_st.evIn, 0);
    // GEMM6a: cbuf = input @ Wout_i^T  (A = cc second half, B = W_out cols [1024:2048))
    gemm_hmma<2, 1024, true, false, false, false>
        <<<dim3(DD / 128, (TD * BD) / 128, 1), 256, SMEM_TOT, s2>>>(
        cc_hi + DD, cc_lo + DD, 2 * DD, 0LL,
        wout_hi + DD, wout_lo + DD, 2 * DD, 0LL,
        cbuf, DD, 0LL, nullptr, nullptr, 0LL, 0LL, nullptr);
    cudaEventRecord(g_st.ev6a, s2);

    // 1) h = input @ W_in^T : K=1024 -> fp16 pair out  (3-term: feeds logits)
    gemm_hmma<3, 1024, false, false, true, false>
        <<<dim3(DD / 128, (BD * TD) / 128, 1), 256, SMEM_TOT>>>(
        in_hi, in_lo, DD, 0LL, win_hi, win_lo, DD, 0LL,
        nullptr, 0LL, 0LL, h_hi, h_lo, DD, 0LL, nullptr);

    // 2) align[b] = h[b] @ ctx[b]^T : K=1024 -> fp32 into [T,B,S]  (3-term: logits)
    cudaStreamWaitEvent(0, g_st.evCtx, 0);
    gemm_hmma<3, 1024, true, false, false, false>
        <<<dim3(SD / 128, TD / 128, BD), 256, SMEM_TOT>>>(
        h_hi, h_lo, DD, (long long)TD * DD, ctx_hi, ctx_lo, DD, (long long)SD * DD,
        alignv, (long long)BD * SD, (long long)SD, nullptr, nullptr, 0LL, 0LL, nullptr);

    // 3) softmax over S + fp16 pair
    softmax1024<<<TD * BD, 256>>>(alignv, av_hi, av_lo);

    // 4) c[b] = av[b] @ ctxT[b]^T : K=1024(S) -> fp32 + pair  (2-term)
    gemm_hmma<2, 1024, true, false, true, false>
        <<<dim3(DD / 128, TD / 128, BD), 256, SMEM_TOT>>>(
        av_hi, av_lo, (long long)BD * SD, (long long)SD,
        ctxT_hi, ctxT_lo, SD, (long long)DD * SD,
        concat, (long long)BD * 2 * DD, (long long)(2 * DD),
        cc_hi, cc_lo, (long long)BD * 2 * DD, (long long)(2 * DD), nullptr);

    // 5) attn = tanh(cbuf + c @ Wout_c^T) : K=1024, acc init from cbuf  (2-term)
    cudaStreamWaitEvent(0, g_st.ev6a, 0);
    gemm_hmma<2, 1024, true, true, false, true>
        <<<dim3(DD / 128, (TD * BD) / 128, 1), 256, SMEM_TOT>>>(
        cc_hi, cc_lo, 2 * DD, 0LL, wout_hi, wout_lo, 2 * DD, 0LL,
        attn, DD, 0LL, nullptr, nullptr, 0LL, 0LL, cbuf);
}